// round 1
// baseline (speedup 1.0000x reference)
#include <cuda_runtime.h>
#include <math.h>

#define Bb 4
#define Ss 2048
#define Dd 1024
#define Hh 16
#define HD 64

// Scratch (device globals; no allocation in kernel_launch)
__device__ float g_q[Bb*Hh*Ss*HD];    // 32 MB, [B,H,S,HD]
__device__ float g_k[Bb*Hh*Ss*HD];    // 32 MB
__device__ float g_v[Bb*Hh*Ss*HD];    // 32 MB
__device__ float g_ctx[Bb*Ss*Dd];     // 32 MB, [B,S,D] (heads concatenated)

// ---------------------------------------------------------------------------
// Kernel 1: fused QKV projection.
// out[b,h,s,e] = sum_d x[b,s,d] * W[h,d,e], W in [H,D,HD].
// Treated as GEMM M=8192 (b*S+s), N=1024 (h*64+e), K=1024. BN=64 aligns to a
// head, so the weight slice W[h] is a contiguous row-major [D,64] matrix.
// Tile: BM=128, BN=64, BK=16, 256 threads, 8x4 per thread.
// ---------------------------------------------------------------------------
__global__ __launch_bounds__(256) void qkv_kernel(
    const float* __restrict__ x,
    const float* __restrict__ Wq,
    const float* __restrict__ Wk,
    const float* __restrict__ Wv)
{
    __shared__ float as[16][132];   // [BK][BM+4], k-major A tile
    __shared__ float bs[16][64];    // [BK][BN]

    const int m0 = blockIdx.x * 128;
    const int h  = blockIdx.y;                 // BN==HD, head-aligned
    const float* W   = (blockIdx.z == 0) ? Wq : (blockIdx.z == 1 ? Wk : Wv);
    float*       out = (blockIdx.z == 0) ? g_q : (blockIdx.z == 1 ? g_k : g_v);
    const float* Wh = W + (size_t)h * Dd * HD; // [D][64] row-major

    const int tid = threadIdx.x;
    const int tx = tid & 15;   // column group: cols tx*4 .. tx*4+3
    const int ty = tid >> 4;   // row group:    rows ty*8 .. ty*8+7

    float acc[8][4];
    #pragma unroll
    for (int i = 0; i < 8; i++)
        #pragma unroll
        for (int j = 0; j < 4; j++) acc[i][j] = 0.f;

    for (int k0 = 0; k0 < Dd; k0 += 16) {
        // A tile: x[(m0+m)][k0..k0+15] -> as[k][m] (transposed in smem)
        #pragma unroll
        for (int it = 0; it < 2; ++it) {
            int i = tid + it * 256;
            int m = i >> 2, kg = i & 3;
            float4 v = *(const float4*)(x + (size_t)(m0 + m) * Dd + k0 + kg * 4);
            as[kg*4+0][m] = v.x; as[kg*4+1][m] = v.y;
            as[kg*4+2][m] = v.z; as[kg*4+3][m] = v.w;
        }
        // B tile: Wh[(k0+k)][n] -> bs[k][n]  (already row-major in n)
        {
            int k = tid >> 4, ng = tid & 15;
            *(float4*)&bs[k][ng*4] =
                *(const float4*)(Wh + (size_t)(k0 + k) * HD + ng * 4);
        }
        __syncthreads();

        #pragma unroll
        for (int k = 0; k < 16; ++k) {
            float a[8], b[4];
            *(float4*)&a[0] = *(const float4*)&as[k][ty*8];
            *(float4*)&a[4] = *(const float4*)&as[k][ty*8 + 4];
            *(float4*)&b[0] = *(const float4*)&bs[k][tx*4];
            #pragma unroll
            for (int i = 0; i < 8; i++)
                #pragma unroll
                for (int j = 0; j < 4; j++)
                    acc[i][j] += a[i] * b[j];
        }
        __syncthreads();
    }

    // Write q/k/v in [B,H,S,HD] layout.
    #pragma unroll
    for (int i = 0; i < 8; i++) {
        int m = m0 + ty * 8 + i;
        int b = m / Ss, s = m % Ss;
        float4 v = make_float4(acc[i][0], acc[i][1], acc[i][2], acc[i][3]);
        *(float4*)(out + ((size_t)(b * Hh + h) * Ss + s) * HD + tx * 4) = v;
    }
}

// ---------------------------------------------------------------------------
// Kernel 2: causal flash attention, fp32, online softmax.
// One block = (b, h, 128-query tile). 128 threads, one query row per thread:
// q[64] and o[64] live in registers; K/V tiles (64x64) in smem (broadcast LDS).
// Causal handled by per-thread jlim (no masking arithmetic at all).
// ---------------------------------------------------------------------------
__global__ __launch_bounds__(128) void attn_kernel()
{
    __shared__ float Ks[64][64];
    __shared__ float Vs[64][64];

    const int b  = blockIdx.z;
    const int h  = blockIdx.y;
    const int qt = (int)gridDim.x - 1 - (int)blockIdx.x; // big tiles first
    const int t  = threadIdx.x;
    const int qrow = qt * 128 + t;
    const size_t bh = (size_t)(b * Hh + h) * Ss;

    float q[64];
    {
        const float* qptr = g_q + (bh + qrow) * HD;
        #pragma unroll
        for (int e = 0; e < 64; e += 4)
            *(float4*)&q[e] = *(const float4*)(qptr + e);
    }
    float o[64];
    #pragma unroll
    for (int e = 0; e < 64; e++) o[e] = 0.f;
    float mv = -1e30f, l = 0.f;

    const int jend = qt * 128 + 128;
    for (int j0 = 0; j0 < jend; j0 += 64) {
        // cooperative K/V tile load (fully coalesced float4)
        const float4* kb = (const float4*)(g_k + (bh + j0) * HD);
        const float4* vb = (const float4*)(g_v + (bh + j0) * HD);
        float4* ks4 = (float4*)&Ks[0][0];
        float4* vs4 = (float4*)&Vs[0][0];
        #pragma unroll
        for (int it = 0; it < 8; ++it) {
            ks4[t + it * 128] = kb[t + it * 128];
            vs4[t + it * 128] = vb[t + it * 128];
        }
        __syncthreads();

        int jlim = qrow - j0 + 1;
        if (jlim > 64) jlim = 64;
        for (int j = 0; j < jlim; ++j) {
            float s0 = 0.f, s1 = 0.f, s2 = 0.f, s3 = 0.f;
            #pragma unroll
            for (int e = 0; e < 64; e += 4) {
                s0 += q[e+0] * Ks[j][e+0];
                s1 += q[e+1] * Ks[j][e+1];
                s2 += q[e+2] * Ks[j][e+2];
                s3 += q[e+3] * Ks[j][e+3];
            }
            float sc = ((s0 + s1) + (s2 + s3)) * 0.125f; // 1/sqrt(64)
            if (sc > mv) {                 // rare: rescale accumulator
                float corr = __expf(mv - sc);
                l *= corr;
                #pragma unroll
                for (int e = 0; e < 64; e++) o[e] *= corr;
                mv = sc;
            }
            float p = __expf(sc - mv);
            l += p;
            #pragma unroll
            for (int e = 0; e < 64; e++) o[e] += p * Vs[j][e];
        }
        __syncthreads();
    }

    const float inv = 1.0f / l;
    float* op = g_ctx + ((size_t)(b * Ss) + qrow) * Dd + h * HD;
    #pragma unroll
    for (int e = 0; e < 64; e += 4) {
        float4 v = make_float4(o[e]*inv, o[e+1]*inv, o[e+2]*inv, o[e+3]*inv);
        *(float4*)(op + e) = v;
    }
}

// ---------------------------------------------------------------------------
// Kernel 3: output projection. y[m][n] = sum_k ctx[m][k] * Wo[n][k] + bo[n].
// Wo is [out,in] (torch Linear), so B must be transposed into smem.
// ---------------------------------------------------------------------------
__global__ __launch_bounds__(256) void oproj_kernel(
    const float* __restrict__ Wo,
    const float* __restrict__ bo,
    float* __restrict__ y)
{
    __shared__ float as[16][132];  // [BK][BM+4]
    __shared__ float bs[16][68];   // [BK][BN+4]

    const int m0 = blockIdx.x * 128;
    const int n0 = blockIdx.y * 64;
    const int tid = threadIdx.x;
    const int tx = tid & 15, ty = tid >> 4;
    const float* A = g_ctx;

    float acc[8][4];
    #pragma unroll
    for (int i = 0; i < 8; i++)
        #pragma unroll
        for (int j = 0; j < 4; j++) acc[i][j] = 0.f;

    for (int k0 = 0; k0 < Dd; k0 += 16) {
        #pragma unroll
        for (int it = 0; it < 2; ++it) {
            int i = tid + it * 256;
            int m = i >> 2, kg = i & 3;
            float4 v = *(const float4*)(A + (size_t)(m0 + m) * Dd + k0 + kg * 4);
            as[kg*4+0][m] = v.x; as[kg*4+1][m] = v.y;
            as[kg*4+2][m] = v.z; as[kg*4+3][m] = v.w;
        }
        {   // Wo[n0+n][k0..k0+15] -> bs[k][n] (transpose)
            int n = tid >> 2, kg = tid & 3;
            float4 w = *(const float4*)(Wo + (size_t)(n0 + n) * Dd + k0 + kg * 4);
            bs[kg*4+0][n] = w.x; bs[kg*4+1][n] = w.y;
            bs[kg*4+2][n] = w.z; bs[kg*4+3][n] = w.w;
        }
        __syncthreads();

        #pragma unroll
        for (int k = 0; k < 16; ++k) {
            float a[8], bvec[4];
            *(float4*)&a[0]    = *(const float4*)&as[k][ty*8];
            *(float4*)&a[4]    = *(const float4*)&as[k][ty*8 + 4];
            *(float4*)&bvec[0] = *(const float4*)&bs[k][tx*4];
            #pragma unroll
            for (int i = 0; i < 8; i++)
                #pragma unroll
                for (int j = 0; j < 4; j++)
                    acc[i][j] += a[i] * bvec[j];
        }
        __syncthreads();
    }

    const float4 bias = *(const float4*)(bo + n0 + tx * 4);
    #pragma unroll
    for (int i = 0; i < 8; i++) {
        int m = m0 + ty * 8 + i;
        float4 v = make_float4(acc[i][0] + bias.x, acc[i][1] + bias.y,
                               acc[i][2] + bias.z, acc[i][3] + bias.w);
        *(float4*)(y + (size_t)m * Dd + n0 + tx * 4) = v;
    }
}

// ---------------------------------------------------------------------------
extern "C" void kernel_launch(void* const* d_in, const int* in_sizes, int n_in,
                              void* d_out, int out_size)
{
    const float* x  = (const float*)d_in[0];
    const float* Wq = (const float*)d_in[1];
    const float* Wk = (const float*)d_in[2];
    const float* Wv = (const float*)d_in[3];
    const float* Wo = (const float*)d_in[4];
    const float* bo = (const float*)d_in[5];
    float* y = (float*)d_out;

    dim3 gq(64, 16, 3);          // M/128, N/64 (heads), {q,k,v}
    qkv_kernel<<<gq, 256>>>(x, Wq, Wk, Wv);

    dim3 ga(16, Hh, Bb);         // q-tiles, heads, batch
    attn_kernel<<<ga, 128>>>();

    dim3 go(64, 16);             // M/128, N/64
    oproj_kernel<<<go, 256>>>(Wo, bo, y);
}

// round 3
// speedup vs baseline: 1.4407x; 1.4407x over previous
#include <cuda_runtime.h>
#include <math.h>
#include <stdint.h>

#define Bb 4
#define Ss 2048
#define Dd 1024
#define Hh 16
#define HD 64

// Scratch (device globals; no allocation anywhere)
__device__ float g_q[Bb*Hh*Ss*HD];      // 32 MB, [B,H,S,HD]
__device__ float g_k[Bb*Hh*Ss*HD];      // 32 MB
__device__ float g_v[Bb*Hh*Ss*HD];      // 32 MB
__device__ float g_ctx[Bb*Ss*Dd];       // 32 MB, [B,S,D]

// ---------------------------------------------------------------------------
__device__ __forceinline__ uint32_t f2tf32(float x) {
    uint32_t r;
    asm("cvt.rna.tf32.f32 %0, %1;" : "=r"(r) : "f"(x));
    return r;
}
__device__ __forceinline__ uint4 cvt4(float4 v) {
    return make_uint4(f2tf32(v.x), f2tf32(v.y), f2tf32(v.z), f2tf32(v.w));
}
__device__ __forceinline__ void mma_tf32(float* d, const uint32_t* a,
                                         const uint32_t* b) {
    asm volatile(
        "mma.sync.aligned.m16n8k8.row.col.f32.tf32.tf32.f32 "
        "{%0,%1,%2,%3}, {%4,%5,%6,%7}, {%8,%9}, {%0,%1,%2,%3};"
        : "+f"(d[0]), "+f"(d[1]), "+f"(d[2]), "+f"(d[3])
        : "r"(a[0]), "r"(a[1]), "r"(a[2]), "r"(a[3]),
          "r"(b[0]), "r"(b[1]));
}

// ---------------------------------------------------------------------------
// tf32 mma.sync GEMM: C[m][n] = sum_k A[m][k]*B[n][k].
// CTA tile 128x128, BK=16, double-buffered smem, reg-staged gmem prefetch.
// QKV=1: A = x, B = W{q,k,v}[h][k][e] (k-row-major per head, loaded directly),
//        C scattered into g_q/g_k/g_v [B,H,S,HD]. grid.y = 24 (3 mtx x 8).
// QKV=0: A = g_ctx, B = Wo[n][k], C = y + bias. grid.y = 8.
// ---------------------------------------------------------------------------
#define SA 20    // A smem row stride (words): gy*20+gx distinct mod 32
#define SB 136   // B smem row stride (words): gx*8+gy distinct mod 32

template<int QKV>
__global__ __launch_bounds__(256, 2) void gemm_mma_kernel(
    const float* __restrict__ X,
    const float* __restrict__ Wq, const float* __restrict__ Wk,
    const float* __restrict__ Wv, const float* __restrict__ Wo,
    const float* __restrict__ bias, float* __restrict__ Cout)
{
    __shared__ uint32_t As[2][128 * SA];
    __shared__ uint32_t Bs[2][16 * SB];

    const int tid = threadIdx.x;
    const int wid = tid >> 5, lane = tid & 31;
    const int wm = wid >> 2, wn = wid & 3;        // 2 x 4 warp grid
    const int gy = lane >> 2, gx = lane & 3;
    const int m0 = blockIdx.x * 128;
    const int nt = blockIdx.y;

    const float* A = QKV ? X : g_ctx;

    const float* Wsel;
    int h0 = 0, n0 = 0;
    if (QKV) {
        const int mtx = nt >> 3;
        Wsel = (mtx == 0) ? Wq : (mtx == 1 ? Wk : Wv);
        h0 = (nt & 7) * 2;                        // 128 cols = 2 heads
    } else {
        Wsel = Wo;
        n0 = nt * 128;
    }

    float d[4][4][4];
    #pragma unroll
    for (int i = 0; i < 4; i++)
        #pragma unroll
        for (int j = 0; j < 4; j++)
            #pragma unroll
            for (int c = 0; c < 4; c++) d[i][j][c] = 0.f;

    // loader mappings
    const int am = tid >> 2, ac = tid & 3;        // A: rows am, am+64
    const int bk = tid >> 5, bn4 = tid & 31;      // B qkv: k rows bk, bk+8
    const int bh = h0 + (bn4 >> 4), be4 = bn4 & 15;
    const int onq = tid & 127;                    // B oproj: n, kq fixed/warp
    const int okq = tid >> 7;                     //   kq = okq, okq+2

    uint4 ra0, ra1, rb0, rb1;

    // ---- preload chunk 0 into buffer 0 ----
    {
        const int k0 = 0;
        ra0 = cvt4(*(const float4*)(A + (size_t)(m0 + am) * Dd + k0 + ac * 4));
        ra1 = cvt4(*(const float4*)(A + (size_t)(m0 + am + 64) * Dd + k0 + ac * 4));
        if (QKV) {
            rb0 = cvt4(*(const float4*)(Wsel + ((size_t)bh * Dd + k0 + bk) * HD + be4 * 4));
            rb1 = cvt4(*(const float4*)(Wsel + ((size_t)bh * Dd + k0 + bk + 8) * HD + be4 * 4));
        } else {
            rb0 = cvt4(*(const float4*)(Wsel + (size_t)(n0 + onq) * Dd + k0 + okq * 4));
            rb1 = cvt4(*(const float4*)(Wsel + (size_t)(n0 + onq) * Dd + k0 + (okq + 2) * 4));
        }
        *(uint4*)&As[0][am * SA + ac * 4] = ra0;
        *(uint4*)&As[0][(am + 64) * SA + ac * 4] = ra1;
        if (QKV) {
            *(uint4*)&Bs[0][bk * SB + bn4 * 4] = rb0;
            *(uint4*)&Bs[0][(bk + 8) * SB + bn4 * 4] = rb1;
        } else {
            Bs[0][(okq * 4 + 0) * SB + onq] = rb0.x;
            Bs[0][(okq * 4 + 1) * SB + onq] = rb0.y;
            Bs[0][(okq * 4 + 2) * SB + onq] = rb0.z;
            Bs[0][(okq * 4 + 3) * SB + onq] = rb0.w;
            Bs[0][((okq + 2) * 4 + 0) * SB + onq] = rb1.x;
            Bs[0][((okq + 2) * 4 + 1) * SB + onq] = rb1.y;
            Bs[0][((okq + 2) * 4 + 2) * SB + onq] = rb1.z;
            Bs[0][((okq + 2) * 4 + 3) * SB + onq] = rb1.w;
        }
    }
    __syncthreads();

    for (int kc = 0; kc < 64; ++kc) {
        const int buf = kc & 1;
        const bool more = (kc + 1 < 64);
        if (more) {
            const int k0 = (kc + 1) * 16;
            ra0 = cvt4(*(const float4*)(A + (size_t)(m0 + am) * Dd + k0 + ac * 4));
            ra1 = cvt4(*(const float4*)(A + (size_t)(m0 + am + 64) * Dd + k0 + ac * 4));
            if (QKV) {
                rb0 = cvt4(*(const float4*)(Wsel + ((size_t)bh * Dd + k0 + bk) * HD + be4 * 4));
                rb1 = cvt4(*(const float4*)(Wsel + ((size_t)bh * Dd + k0 + bk + 8) * HD + be4 * 4));
            } else {
                rb0 = cvt4(*(const float4*)(Wsel + (size_t)(n0 + onq) * Dd + k0 + okq * 4));
                rb1 = cvt4(*(const float4*)(Wsel + (size_t)(n0 + onq) * Dd + k0 + (okq + 2) * 4));
            }
        }

        // ---- compute on buf ----
        const uint32_t* as = &As[buf][0];
        const uint32_t* bs = &Bs[buf][0];
        #pragma unroll
        for (int kk = 0; kk < 2; ++kk) {
            const int k8 = kk * 8;
            uint32_t af[4][4], bf[4][2];
            #pragma unroll
            for (int ti = 0; ti < 4; ++ti) {
                const int rm = wm * 64 + ti * 16;
                af[ti][0] = as[(rm + gy) * SA + k8 + gx];
                af[ti][1] = as[(rm + gy + 8) * SA + k8 + gx];
                af[ti][2] = as[(rm + gy) * SA + k8 + gx + 4];
                af[ti][3] = as[(rm + gy + 8) * SA + k8 + gx + 4];
            }
            #pragma unroll
            for (int tj = 0; tj < 4; ++tj) {
                const int cn = wn * 32 + tj * 8;
                bf[tj][0] = bs[(k8 + gx) * SB + cn + gy];
                bf[tj][1] = bs[(k8 + gx + 4) * SB + cn + gy];
            }
            #pragma unroll
            for (int ti = 0; ti < 4; ++ti)
                #pragma unroll
                for (int tj = 0; tj < 4; ++tj)
                    mma_tf32(d[ti][tj], af[ti], bf[tj]);
        }

        if (more) {
            const int nb = buf ^ 1;
            *(uint4*)&As[nb][am * SA + ac * 4] = ra0;
            *(uint4*)&As[nb][(am + 64) * SA + ac * 4] = ra1;
            if (QKV) {
                *(uint4*)&Bs[nb][bk * SB + bn4 * 4] = rb0;
                *(uint4*)&Bs[nb][(bk + 8) * SB + bn4 * 4] = rb1;
            } else {
                Bs[nb][(okq * 4 + 0) * SB + onq] = rb0.x;
                Bs[nb][(okq * 4 + 1) * SB + onq] = rb0.y;
                Bs[nb][(okq * 4 + 2) * SB + onq] = rb0.z;
                Bs[nb][(okq * 4 + 3) * SB + onq] = rb0.w;
                Bs[nb][((okq + 2) * 4 + 0) * SB + onq] = rb1.x;
                Bs[nb][((okq + 2) * 4 + 1) * SB + onq] = rb1.y;
                Bs[nb][((okq + 2) * 4 + 2) * SB + onq] = rb1.z;
                Bs[nb][((okq + 2) * 4 + 3) * SB + onq] = rb1.w;
            }
        }
        __syncthreads();
    }

    // ---- epilogue ----
    if (QKV) {
        const int mtx = nt >> 3;
        float* out = (mtx == 0) ? g_q : (mtx == 1 ? g_k : g_v);
        #pragma unroll
        for (int ti = 0; ti < 4; ++ti) {
            #pragma unroll
            for (int tj = 0; tj < 4; ++tj) {
                const int colw = (nt & 7) * 128 + wn * 32 + tj * 8 + gx * 2;
                const int h = colw >> 6, e = colw & 63;
                const int r0 = m0 + wm * 64 + ti * 16 + gy;
                const int b0r = r0 >> 11, s0r = r0 & 2047;
                *(float2*)(out + (((size_t)(b0r * Hh + h) * Ss + s0r) * HD + e)) =
                    make_float2(d[ti][tj][0], d[ti][tj][1]);
                const int r1 = r0 + 8;
                const int b1r = r1 >> 11, s1r = r1 & 2047;
                *(float2*)(out + (((size_t)(b1r * Hh + h) * Ss + s1r) * HD + e)) =
                    make_float2(d[ti][tj][2], d[ti][tj][3]);
            }
        }
    } else {
        #pragma unroll
        for (int ti = 0; ti < 4; ++ti) {
            #pragma unroll
            for (int tj = 0; tj < 4; ++tj) {
                const int col = n0 + wn * 32 + tj * 8 + gx * 2;
                const float2 bv = *(const float2*)(bias + col);
                const int r0 = m0 + wm * 64 + ti * 16 + gy;
                *(float2*)(Cout + (size_t)r0 * Dd + col) =
                    make_float2(d[ti][tj][0] + bv.x, d[ti][tj][1] + bv.y);
                *(float2*)(Cout + (size_t)(r0 + 8) * Dd + col) =
                    make_float2(d[ti][tj][2] + bv.x, d[ti][tj][3] + bv.y);
            }
        }
    }
}

// ---------------------------------------------------------------------------
// Causal flash attention, fp32, online softmax (unchanged from R1, passing).
// ---------------------------------------------------------------------------
#define ATTN_BODY(J) do {                                              \
    float s0 = 0.f, s1 = 0.f, s2 = 0.f, s3 = 0.f;                      \
    _Pragma("unroll")                                                  \
    for (int e = 0; e < 64; e += 4) {                                  \
        s0 += q[e+0] * Ks[J][e+0];                                     \
        s1 += q[e+1] * Ks[J][e+1];                                     \
        s2 += q[e+2] * Ks[J][e+2];                                     \
        s3 += q[e+3] * Ks[J][e+3];                                     \
    }                                                                  \
    float sc = ((s0 + s1) + (s2 + s3)) * 0.125f;                       \
    if (sc > mv) {                                                     \
        float corr = __expf(mv - sc);                                  \
        l *= corr;                                                     \
        _Pragma("unroll")                                              \
        for (int e = 0; e < 64; e++) o[e] *= corr;                     \
        mv = sc;                                                       \
    }                                                                  \
    float p = __expf(sc - mv);                                         \
    l += p;                                                            \
    _Pragma("unroll")                                                  \
    for (int e = 0; e < 64; e++) o[e] += p * Vs[J][e];                 \
} while (0)

__global__ __launch_bounds__(128) void attn_kernel()
{
    __shared__ float Ks[64][64];
    __shared__ float Vs[64][64];

    const int b  = blockIdx.z;
    const int h  = blockIdx.y;
    const int qt = (int)gridDim.x - 1 - (int)blockIdx.x;  // big tiles first
    const int t  = threadIdx.x;
    const int qrow = qt * 128 + t;
    const size_t bh = (size_t)(b * Hh + h) * Ss;

    float q[64];
    {
        const float* qptr = g_q + (bh + qrow) * HD;
        #pragma unroll
        for (int e = 0; e < 64; e += 4)
            *(float4*)&q[e] = *(const float4*)(qptr + e);
    }
    float o[64];
    #pragma unroll
    for (int e = 0; e < 64; e++) o[e] = 0.f;
    float mv = -1e30f, l = 0.f;

    const int nfull = qt * 2;
    for (int t64 = 0; t64 < nfull + 2; ++t64) {
        const int j0 = t64 * 64;
        const float4* kb = (const float4*)(g_k + (bh + j0) * HD);
        const float4* vb = (const float4*)(g_v + (bh + j0) * HD);
        float4* ks4 = (float4*)&Ks[0][0];
        float4* vs4 = (float4*)&Vs[0][0];
        #pragma unroll
        for (int it = 0; it < 8; ++it) {
            ks4[t + it * 128] = kb[t + it * 128];
            vs4[t + it * 128] = vb[t + it * 128];
        }
        __syncthreads();

        if (t64 < nfull) {
            #pragma unroll 2
            for (int j = 0; j < 64; ++j) ATTN_BODY(j);
        } else {
            int jlim = qrow - j0 + 1;
            if (jlim > 64) jlim = 64;
            for (int j = 0; j < jlim; ++j) ATTN_BODY(j);
        }
        __syncthreads();
    }

    const float inv = 1.0f / l;
    float* op = g_ctx + ((size_t)(b * Ss) + qrow) * Dd + h * HD;
    #pragma unroll
    for (int e = 0; e < 64; e += 4) {
        float4 v = make_float4(o[e]*inv, o[e+1]*inv, o[e+2]*inv, o[e+3]*inv);
        *(float4*)(op + e) = v;
    }
}

// ---------------------------------------------------------------------------
extern "C" void kernel_launch(void* const* d_in, const int* in_sizes, int n_in,
                              void* d_out, int out_size)
{
    const float* x  = (const float*)d_in[0];
    const float* Wq = (const float*)d_in[1];
    const float* Wk = (const float*)d_in[2];
    const float* Wv = (const float*)d_in[3];
    const float* Wo = (const float*)d_in[4];
    const float* bo = (const float*)d_in[5];
    float* y = (float*)d_out;

    dim3 gq(64, 24);     // M/128, 3 matrices x 8 n-tiles
    gemm_mma_kernel<1><<<gq, 256>>>(x, Wq, Wk, Wv, nullptr, nullptr, nullptr);

    dim3 ga(16, Hh, Bb); // q-tiles, heads, batch
    attn_kernel<<<ga, 128>>>();

    dim3 go(64, 8);      // M/128, N/128
    gemm_mma_kernel<0><<<go, 256>>>(nullptr, nullptr, nullptr, nullptr, Wo, bo, y);
}

// round 4
// speedup vs baseline: 2.8014x; 1.9445x over previous
#include <cuda_runtime.h>
#include <math.h>
#include <stdint.h>

#define Bb 4
#define Ss 2048
#define Dd 1024
#define Hh 16
#define HD 64

// Scratch (device globals; no allocation anywhere)
__device__ float g_q[Bb*Hh*Ss*HD];      // 32 MB, [B,H,S,HD]
__device__ float g_k[Bb*Hh*Ss*HD];      // 32 MB
__device__ float g_v[Bb*Hh*Ss*HD];      // 32 MB
__device__ float g_ctx[Bb*Ss*Dd];       // 32 MB, [B,S,D]

// ---------------------------------------------------------------------------
__device__ __forceinline__ uint32_t f2tf32(float x) {
    uint32_t r;
    asm("cvt.rna.tf32.f32 %0, %1;" : "=r"(r) : "f"(x));
    return r;
}
__device__ __forceinline__ uint4 cvt4(float4 v) {
    return make_uint4(f2tf32(v.x), f2tf32(v.y), f2tf32(v.z), f2tf32(v.w));
}
__device__ __forceinline__ void mma_tf32(float* d, const uint32_t* a,
                                         const uint32_t* b) {
    asm volatile(
        "mma.sync.aligned.m16n8k8.row.col.f32.tf32.tf32.f32 "
        "{%0,%1,%2,%3}, {%4,%5,%6,%7}, {%8,%9}, {%0,%1,%2,%3};"
        : "+f"(d[0]), "+f"(d[1]), "+f"(d[2]), "+f"(d[3])
        : "r"(a[0]), "r"(a[1]), "r"(a[2]), "r"(a[3]),
          "r"(b[0]), "r"(b[1]));
}

// ---------------------------------------------------------------------------
// tf32 mma.sync GEMM (unchanged from R3; passing)
// ---------------------------------------------------------------------------
#define SA 20
#define SB 136

template<int QKV>
__global__ __launch_bounds__(256, 2) void gemm_mma_kernel(
    const float* __restrict__ X,
    const float* __restrict__ Wq, const float* __restrict__ Wk,
    const float* __restrict__ Wv, const float* __restrict__ Wo,
    const float* __restrict__ bias, float* __restrict__ Cout)
{
    __shared__ uint32_t As[2][128 * SA];
    __shared__ uint32_t Bs[2][16 * SB];

    const int tid = threadIdx.x;
    const int wid = tid >> 5, lane = tid & 31;
    const int wm = wid >> 2, wn = wid & 3;
    const int gy = lane >> 2, gx = lane & 3;
    const int m0 = blockIdx.x * 128;
    const int nt = blockIdx.y;

    const float* A = QKV ? X : g_ctx;

    const float* Wsel;
    int h0 = 0, n0 = 0;
    if (QKV) {
        const int mtx = nt >> 3;
        Wsel = (mtx == 0) ? Wq : (mtx == 1 ? Wk : Wv);
        h0 = (nt & 7) * 2;
    } else {
        Wsel = Wo;
        n0 = nt * 128;
    }

    float d[4][4][4];
    #pragma unroll
    for (int i = 0; i < 4; i++)
        #pragma unroll
        for (int j = 0; j < 4; j++)
            #pragma unroll
            for (int c = 0; c < 4; c++) d[i][j][c] = 0.f;

    const int am = tid >> 2, ac = tid & 3;
    const int bk = tid >> 5, bn4 = tid & 31;
    const int bh = h0 + (bn4 >> 4), be4 = bn4 & 15;
    const int onq = tid & 127;
    const int okq = tid >> 7;

    uint4 ra0, ra1, rb0, rb1;

    {
        const int k0 = 0;
        ra0 = cvt4(*(const float4*)(A + (size_t)(m0 + am) * Dd + k0 + ac * 4));
        ra1 = cvt4(*(const float4*)(A + (size_t)(m0 + am + 64) * Dd + k0 + ac * 4));
        if (QKV) {
            rb0 = cvt4(*(const float4*)(Wsel + ((size_t)bh * Dd + k0 + bk) * HD + be4 * 4));
            rb1 = cvt4(*(const float4*)(Wsel + ((size_t)bh * Dd + k0 + bk + 8) * HD + be4 * 4));
        } else {
            rb0 = cvt4(*(const float4*)(Wsel + (size_t)(n0 + onq) * Dd + k0 + okq * 4));
            rb1 = cvt4(*(const float4*)(Wsel + (size_t)(n0 + onq) * Dd + k0 + (okq + 2) * 4));
        }
        *(uint4*)&As[0][am * SA + ac * 4] = ra0;
        *(uint4*)&As[0][(am + 64) * SA + ac * 4] = ra1;
        if (QKV) {
            *(uint4*)&Bs[0][bk * SB + bn4 * 4] = rb0;
            *(uint4*)&Bs[0][(bk + 8) * SB + bn4 * 4] = rb1;
        } else {
            Bs[0][(okq * 4 + 0) * SB + onq] = rb0.x;
            Bs[0][(okq * 4 + 1) * SB + onq] = rb0.y;
            Bs[0][(okq * 4 + 2) * SB + onq] = rb0.z;
            Bs[0][(okq * 4 + 3) * SB + onq] = rb0.w;
            Bs[0][((okq + 2) * 4 + 0) * SB + onq] = rb1.x;
            Bs[0][((okq + 2) * 4 + 1) * SB + onq] = rb1.y;
            Bs[0][((okq + 2) * 4 + 2) * SB + onq] = rb1.z;
            Bs[0][((okq + 2) * 4 + 3) * SB + onq] = rb1.w;
        }
    }
    __syncthreads();

    for (int kc = 0; kc < 64; ++kc) {
        const int buf = kc & 1;
        const bool more = (kc + 1 < 64);
        if (more) {
            const int k0 = (kc + 1) * 16;
            ra0 = cvt4(*(const float4*)(A + (size_t)(m0 + am) * Dd + k0 + ac * 4));
            ra1 = cvt4(*(const float4*)(A + (size_t)(m0 + am + 64) * Dd + k0 + ac * 4));
            if (QKV) {
                rb0 = cvt4(*(const float4*)(Wsel + ((size_t)bh * Dd + k0 + bk) * HD + be4 * 4));
                rb1 = cvt4(*(const float4*)(Wsel + ((size_t)bh * Dd + k0 + bk + 8) * HD + be4 * 4));
            } else {
                rb0 = cvt4(*(const float4*)(Wsel + (size_t)(n0 + onq) * Dd + k0 + okq * 4));
                rb1 = cvt4(*(const float4*)(Wsel + (size_t)(n0 + onq) * Dd + k0 + (okq + 2) * 4));
            }
        }

        const uint32_t* as = &As[buf][0];
        const uint32_t* bs = &Bs[buf][0];
        #pragma unroll
        for (int kk = 0; kk < 2; ++kk) {
            const int k8 = kk * 8;
            uint32_t af[4][4], bf[4][2];
            #pragma unroll
            for (int ti = 0; ti < 4; ++ti) {
                const int rm = wm * 64 + ti * 16;
                af[ti][0] = as[(rm + gy) * SA + k8 + gx];
                af[ti][1] = as[(rm + gy + 8) * SA + k8 + gx];
                af[ti][2] = as[(rm + gy) * SA + k8 + gx + 4];
                af[ti][3] = as[(rm + gy + 8) * SA + k8 + gx + 4];
            }
            #pragma unroll
            for (int tj = 0; tj < 4; ++tj) {
                const int cn = wn * 32 + tj * 8;
                bf[tj][0] = bs[(k8 + gx) * SB + cn + gy];
                bf[tj][1] = bs[(k8 + gx + 4) * SB + cn + gy];
            }
            #pragma unroll
            for (int ti = 0; ti < 4; ++ti)
                #pragma unroll
                for (int tj = 0; tj < 4; ++tj)
                    mma_tf32(d[ti][tj], af[ti], bf[tj]);
        }

        if (more) {
            const int nb = buf ^ 1;
            *(uint4*)&As[nb][am * SA + ac * 4] = ra0;
            *(uint4*)&As[nb][(am + 64) * SA + ac * 4] = ra1;
            if (QKV) {
                *(uint4*)&Bs[nb][bk * SB + bn4 * 4] = rb0;
                *(uint4*)&Bs[nb][(bk + 8) * SB + bn4 * 4] = rb1;
            } else {
                Bs[nb][(okq * 4 + 0) * SB + onq] = rb0.x;
                Bs[nb][(okq * 4 + 1) * SB + onq] = rb0.y;
                Bs[nb][(okq * 4 + 2) * SB + onq] = rb0.z;
                Bs[nb][(okq * 4 + 3) * SB + onq] = rb0.w;
                Bs[nb][((okq + 2) * 4 + 0) * SB + onq] = rb1.x;
                Bs[nb][((okq + 2) * 4 + 1) * SB + onq] = rb1.y;
                Bs[nb][((okq + 2) * 4 + 2) * SB + onq] = rb1.z;
                Bs[nb][((okq + 2) * 4 + 3) * SB + onq] = rb1.w;
            }
        }
        __syncthreads();
    }

    if (QKV) {
        const int mtx = nt >> 3;
        float* out = (mtx == 0) ? g_q : (mtx == 1 ? g_k : g_v);
        #pragma unroll
        for (int ti = 0; ti < 4; ++ti) {
            #pragma unroll
            for (int tj = 0; tj < 4; ++tj) {
                const int colw = (nt & 7) * 128 + wn * 32 + tj * 8 + gx * 2;
                const int h = colw >> 6, e = colw & 63;
                const int r0 = m0 + wm * 64 + ti * 16 + gy;
                const int b0r = r0 >> 11, s0r = r0 & 2047;
                *(float2*)(out + (((size_t)(b0r * Hh + h) * Ss + s0r) * HD + e)) =
                    make_float2(d[ti][tj][0], d[ti][tj][1]);
                const int r1 = r0 + 8;
                const int b1r = r1 >> 11, s1r = r1 & 2047;
                *(float2*)(out + (((size_t)(b1r * Hh + h) * Ss + s1r) * HD + e)) =
                    make_float2(d[ti][tj][2], d[ti][tj][3]);
            }
        }
    } else {
        #pragma unroll
        for (int ti = 0; ti < 4; ++ti) {
            #pragma unroll
            for (int tj = 0; tj < 4; ++tj) {
                const int col = n0 + wn * 32 + tj * 8 + gx * 2;
                const float2 bv = *(const float2*)(bias + col);
                const int r0 = m0 + wm * 64 + ti * 16 + gy;
                *(float2*)(Cout + (size_t)r0 * Dd + col) =
                    make_float2(d[ti][tj][0] + bv.x, d[ti][tj][1] + bv.y);
                *(float2*)(Cout + (size_t)(r0 + 8) * Dd + col) =
                    make_float2(d[ti][tj][2] + bv.x, d[ti][tj][3] + bv.y);
            }
        }
    }
}

// ---------------------------------------------------------------------------
// tf32 mma.sync causal flash attention.
// CTA = (qtile 128, h, b), 8 warps x 16 q-rows. K/V 64x64 tiles in smem
// stored naturally ([j][e]) — that layout IS the B-fragment layout for both
// mmas. Strides chosen for conflict-free fragment reads.
// ---------------------------------------------------------------------------
#define STK 68
#define STV 76
#define STP 76
#define ATTN_SMEM ((64*STK + 64*STV + 8*16*STP) * 4)

__global__ __launch_bounds__(256) void attn_mma_kernel()
{
    extern __shared__ uint32_t sm[];
    uint32_t* Ksn = sm;                       // [64][STK], K tile [j][e]
    uint32_t* Vs  = sm + 64 * STK;            // [64][STV], V tile [j][e]
    const int tid = threadIdx.x, wid = tid >> 5, lane = tid & 31;
    const int gy = lane >> 2, gx = lane & 3;
    uint32_t* Ps = sm + 64 * STK + 64 * STV + wid * 16 * STP;  // per-warp P/Q

    const int b = blockIdx.z, h = blockIdx.y;
    const int qt = (int)gridDim.x - 1 - (int)blockIdx.x;   // big tiles first
    const int qbase = qt * 128 + wid * 16;
    const size_t bhofs = (size_t)(b * Hh + h) * Ss;

    // Stage warp's Q tile (16x64, pre-scaled 1/8, tf32) through Ps, frag-load.
    {
        const float* Qg = g_q + (bhofs + qbase) * HD;
        #pragma unroll
        for (int i = 0; i < 8; ++i) {
            int idx = i * 32 + lane;
            int r = idx >> 4, c4 = idx & 15;
            float4 v = *(const float4*)(Qg + (size_t)r * HD + c4 * 4);
            uint4 u = make_uint4(f2tf32(v.x * 0.125f), f2tf32(v.y * 0.125f),
                                 f2tf32(v.z * 0.125f), f2tf32(v.w * 0.125f));
            *(uint4*)&Ps[r * STP + c4 * 4] = u;
        }
        __syncwarp();
    }
    uint32_t qf[8][4];
    #pragma unroll
    for (int kk = 0; kk < 8; ++kk) {
        const int k8 = kk * 8;
        qf[kk][0] = Ps[gy * STP + k8 + gx];
        qf[kk][1] = Ps[(gy + 8) * STP + k8 + gx];
        qf[kk][2] = Ps[gy * STP + k8 + gx + 4];
        qf[kk][3] = Ps[(gy + 8) * STP + k8 + gx + 4];
    }
    __syncwarp();

    float oa[8][4];
    #pragma unroll
    for (int tn = 0; tn < 8; ++tn)
        #pragma unroll
        for (int c = 0; c < 4; ++c) oa[tn][c] = 0.f;
    float m0 = -1e30f, m1 = -1e30f, l0 = 0.f, l1 = 0.f;

    const int ntiles = qt * 2 + 2;
    for (int t64 = 0; t64 < ntiles; ++t64) {
        const int j0 = t64 * 64;
        __syncthreads();   // previous-tile reads done before overwrite
        {
            const float* Kg = g_k + (bhofs + j0) * HD;
            const float* Vg = g_v + (bhofs + j0) * HD;
            #pragma unroll
            for (int i = 0; i < 4; ++i) {
                int idx = i * 256 + tid;
                int r = idx >> 4, c4 = idx & 15;
                float4 kv = *(const float4*)(Kg + (size_t)r * HD + c4 * 4);
                *(uint4*)&Ksn[r * STK + c4 * 4] = cvt4(kv);
                float4 vv = *(const float4*)(Vg + (size_t)r * HD + c4 * 4);
                *(uint4*)&Vs[r * STV + c4 * 4] = cvt4(vv);
            }
        }
        __syncthreads();
        if (j0 > qbase + 15) continue;   // tile fully masked for this warp

        // ---- S = Q @ K^T (scaled) ----
        float s[8][4];
        #pragma unroll
        for (int tj = 0; tj < 8; ++tj)
            #pragma unroll
            for (int c = 0; c < 4; ++c) s[tj][c] = 0.f;
        #pragma unroll
        for (int kk = 0; kk < 8; ++kk) {
            const int k8 = kk * 8;
            #pragma unroll
            for (int tj = 0; tj < 8; ++tj) {
                uint32_t bf[2];
                bf[0] = Ksn[(tj * 8 + gy) * STK + k8 + gx];
                bf[1] = Ksn[(tj * 8 + gy) * STK + k8 + gx + 4];
                mma_tf32(s[tj], qf[kk], bf);
            }
        }

        const int r0 = qbase + gy, r1 = r0 + 8;
        if (j0 + 63 > qbase) {   // boundary tile: elementwise causal mask
            #pragma unroll
            for (int tj = 0; tj < 8; ++tj) {
                const int c = j0 + tj * 8 + gx * 2;
                if (c     > r0) s[tj][0] = -1e30f;
                if (c + 1 > r0) s[tj][1] = -1e30f;
                if (c     > r1) s[tj][2] = -1e30f;
                if (c + 1 > r1) s[tj][3] = -1e30f;
            }
        }

        // ---- online softmax ----
        float mx0 = -1e30f, mx1 = -1e30f;
        #pragma unroll
        for (int tj = 0; tj < 8; ++tj) {
            mx0 = fmaxf(mx0, fmaxf(s[tj][0], s[tj][1]));
            mx1 = fmaxf(mx1, fmaxf(s[tj][2], s[tj][3]));
        }
        mx0 = fmaxf(mx0, __shfl_xor_sync(0xFFFFFFFFu, mx0, 1));
        mx0 = fmaxf(mx0, __shfl_xor_sync(0xFFFFFFFFu, mx0, 2));
        mx1 = fmaxf(mx1, __shfl_xor_sync(0xFFFFFFFFu, mx1, 1));
        mx1 = fmaxf(mx1, __shfl_xor_sync(0xFFFFFFFFu, mx1, 2));
        const float nm0 = fmaxf(m0, mx0), nm1 = fmaxf(m1, mx1);
        const float cr0 = __expf(m0 - nm0), cr1 = __expf(m1 - nm1);
        m0 = nm0; m1 = nm1;

        float sum0 = 0.f, sum1 = 0.f;
        #pragma unroll
        for (int tj = 0; tj < 8; ++tj) {
            const int cb = tj * 8 + gx * 2;
            float p0 = __expf(s[tj][0] - m0);
            float p1 = __expf(s[tj][1] - m0);
            float p2 = __expf(s[tj][2] - m1);
            float p3 = __expf(s[tj][3] - m1);
            sum0 += p0 + p1;
            sum1 += p2 + p3;
            Ps[gy * STP + cb]           = f2tf32(p0);
            Ps[gy * STP + cb + 1]       = f2tf32(p1);
            Ps[(gy + 8) * STP + cb]     = f2tf32(p2);
            Ps[(gy + 8) * STP + cb + 1] = f2tf32(p3);
        }
        sum0 += __shfl_xor_sync(0xFFFFFFFFu, sum0, 1);
        sum0 += __shfl_xor_sync(0xFFFFFFFFu, sum0, 2);
        sum1 += __shfl_xor_sync(0xFFFFFFFFu, sum1, 1);
        sum1 += __shfl_xor_sync(0xFFFFFFFFu, sum1, 2);
        l0 = l0 * cr0 + sum0;
        l1 = l1 * cr1 + sum1;

        #pragma unroll
        for (int tn = 0; tn < 8; ++tn) {
            oa[tn][0] *= cr0; oa[tn][1] *= cr0;
            oa[tn][2] *= cr1; oa[tn][3] *= cr1;
        }
        __syncwarp();

        // ---- O += P @ V ----
        #pragma unroll
        for (int kk = 0; kk < 8; ++kk) {
            const int k8 = kk * 8;
            uint32_t af[4];
            af[0] = Ps[gy * STP + k8 + gx];
            af[1] = Ps[(gy + 8) * STP + k8 + gx];
            af[2] = Ps[gy * STP + k8 + gx + 4];
            af[3] = Ps[(gy + 8) * STP + k8 + gx + 4];
            #pragma unroll
            for (int tn = 0; tn < 8; ++tn) {
                uint32_t bf[2];
                bf[0] = Vs[(k8 + gx) * STV + tn * 8 + gy];
                bf[1] = Vs[(k8 + gx + 4) * STV + tn * 8 + gy];
                mma_tf32(oa[tn], af, bf);
            }
        }
    }

    // ---- normalize & store to g_ctx [B,S,D] ----
    const float inv0 = 1.0f / l0, inv1 = 1.0f / l1;
    const int r0 = qbase + gy, r1 = r0 + 8;
    #pragma unroll
    for (int tn = 0; tn < 8; ++tn) {
        const int col = h * HD + tn * 8 + gx * 2;
        *(float2*)(g_ctx + (size_t)(b * Ss + r0) * Dd + col) =
            make_float2(oa[tn][0] * inv0, oa[tn][1] * inv0);
        *(float2*)(g_ctx + (size_t)(b * Ss + r1) * Dd + col) =
            make_float2(oa[tn][2] * inv1, oa[tn][3] * inv1);
    }
}

// ---------------------------------------------------------------------------
extern "C" void kernel_launch(void* const* d_in, const int* in_sizes, int n_in,
                              void* d_out, int out_size)
{
    const float* x  = (const float*)d_in[0];
    const float* Wq = (const float*)d_in[1];
    const float* Wk = (const float*)d_in[2];
    const float* Wv = (const float*)d_in[3];
    const float* Wo = (const float*)d_in[4];
    const float* bo = (const float*)d_in[5];
    float* y = (float*)d_out;

    cudaFuncSetAttribute(attn_mma_kernel,
                         cudaFuncAttributeMaxDynamicSharedMemorySize, ATTN_SMEM);

    dim3 gq(64, 24);
    gemm_mma_kernel<1><<<gq, 256>>>(x, Wq, Wk, Wv, nullptr, nullptr, nullptr);

    dim3 ga(16, Hh, Bb);
    attn_mma_kernel<<<ga, 256, ATTN_SMEM>>>();

    dim3 go(64, 8);
    gemm_mma_kernel<0><<<go, 256>>>(nullptr, nullptr, nullptr, nullptr, Wo, bo, y);
}

// round 5
// speedup vs baseline: 4.9130x; 1.7537x over previous
#include <cuda_runtime.h>
#include <cuda_fp16.h>
#include <math.h>
#include <stdint.h>

#define Bb 4
#define Ss 2048
#define Dd 1024
#define Hh 16
#define HD 64

// Scratch (device globals; fp16 to halve traffic)
__device__ __half g_q[Bb*Hh*Ss*HD];     // [B,H,S,HD], pre-scaled by 1/8
__device__ __half g_k[Bb*Hh*Ss*HD];
__device__ __half g_v[Bb*Hh*Ss*HD];
__device__ __half g_ctx[Bb*Ss*Dd];      // [B,S,D]

// ---------------------------------------------------------------------------
__device__ __forceinline__ uint32_t smem_u32(const void* p) {
    uint32_t a;
    asm("{ .reg .u64 t; cvta.to.shared.u64 t, %1; cvt.u32.u64 %0, t; }"
        : "=r"(a) : "l"(p));
    return a;
}
__device__ __forceinline__ uint32_t h2u(float a, float b) {
    __half2 h = __floats2half2_rn(a, b);      // low = a
    return *(uint32_t*)&h;
}
__device__ __forceinline__ void mma_f16(float* d, const uint32_t* a,
                                        const uint32_t* b) {
    asm volatile(
        "mma.sync.aligned.m16n8k16.row.col.f32.f16.f16.f32 "
        "{%0,%1,%2,%3}, {%4,%5,%6,%7}, {%8,%9}, {%0,%1,%2,%3};"
        : "+f"(d[0]), "+f"(d[1]), "+f"(d[2]), "+f"(d[3])
        : "r"(a[0]), "r"(a[1]), "r"(a[2]), "r"(a[3]),
          "r"(b[0]), "r"(b[1]));
}
__device__ __forceinline__ void ldsm4(uint32_t* r, uint32_t a) {
    asm volatile("ldmatrix.sync.aligned.m8n8.x4.shared.b16 {%0,%1,%2,%3}, [%4];"
                 : "=r"(r[0]), "=r"(r[1]), "=r"(r[2]), "=r"(r[3]) : "r"(a));
}
__device__ __forceinline__ void ldsm4t(uint32_t* r, uint32_t a) {
    asm volatile("ldmatrix.sync.aligned.m8n8.x4.trans.shared.b16 {%0,%1,%2,%3}, [%4];"
                 : "=r"(r[0]), "=r"(r[1]), "=r"(r[2]), "=r"(r[3]) : "r"(a));
}

// ---------------------------------------------------------------------------
// fp16 mma GEMM: C[m][n] = sum_k A[m][k]*B[n][k]. CTA 128x128, BK=16.
// A smem: [row][k2] half2-words, stride SAW=12 (ldmatrix-friendly, 48B rows).
// B smem: [k2][n]  half2-words (pairs along k), stride SBW=136.
// QKV=1: A = x (fp32), B = W{q,k,v}[h][k][e]; out -> g_q/g_k/g_v (half).
// QKV=0: A = g_ctx (half), B = Wo[n][k] (fp32); out = y (fp32) + bias.
// ---------------------------------------------------------------------------
#define SAW 12
#define SBW 136

template<int QKV>
__global__ __launch_bounds__(256, 2) void gemm_f16_kernel(
    const float* __restrict__ X,
    const float* __restrict__ Wq, const float* __restrict__ Wk,
    const float* __restrict__ Wv, const float* __restrict__ Wo,
    const float* __restrict__ bias, float* __restrict__ Cout)
{
    __shared__ uint32_t As[2][128 * SAW];
    __shared__ uint32_t Bs[2][8 * SBW];

    const int tid = threadIdx.x;
    const int wid = tid >> 5, lane = tid & 31;
    const int wm = wid >> 2, wn = wid & 3;        // 2 x 4 warp grid
    const int gy = lane >> 2, gx = lane & 3;
    const int m0 = blockIdx.x * 128;
    const int nt = blockIdx.y;

    const float* Wsel;
    int h0 = 0, n0 = 0, mtx = 0;
    if (QKV) {
        mtx = nt >> 3;
        Wsel = (mtx == 0) ? Wq : (mtx == 1 ? Wk : Wv);
        h0 = (nt & 7) * 2;
    } else {
        Wsel = Wo;
        n0 = nt * 128;
    }

    float d[4][4][4];
    #pragma unroll
    for (int i = 0; i < 4; i++)
        #pragma unroll
        for (int j = 0; j < 4; j++)
            #pragma unroll
            for (int c = 0; c < 4; c++) d[i][j][c] = 0.f;

    // loader mappings
    const int am = tid >> 2, ac = tid & 3;        // QKV A
    const int orow = tid >> 1, owq = tid & 1;     // oproj A
    const int k2r = tid >> 5, n4 = tid & 31;      // QKV B
    const int bh = h0 + (n4 >> 4), be = (n4 & 15) * 4;
    const int onq = tid & 127, okq = tid >> 7;    // oproj B

    // ldmatrix lane addressing for A fragments
    const int a_lrow = ((lane >> 3) & 1) * 8 + (lane & 7);
    const int a_lkw  = (lane >> 4) * 4;
    const uint32_t asu = smem_u32(&As[0][0]);
    const uint32_t ABUF = 128 * SAW * 4;

    uint4 ra, rb;

    // ---- preload chunk 0 ----
    {
        const int k0 = 0;
        if (QKV) {
            float4 v0 = *(const float4*)(X + (size_t)(m0 + am) * Dd + k0 + ac * 4);
            float4 v1 = *(const float4*)(X + (size_t)(m0 + am + 64) * Dd + k0 + ac * 4);
            ra = make_uint4(h2u(v0.x, v0.y), h2u(v0.z, v0.w),
                            h2u(v1.x, v1.y), h2u(v1.z, v1.w));
            float4 w0 = *(const float4*)(Wsel + ((size_t)bh * Dd + k0 + 2 * k2r) * HD + be);
            float4 w1 = *(const float4*)(Wsel + ((size_t)bh * Dd + k0 + 2 * k2r + 1) * HD + be);
            rb = make_uint4(h2u(w0.x, w1.x), h2u(w0.y, w1.y),
                            h2u(w0.z, w1.z), h2u(w0.w, w1.w));
        } else {
            ra = *(const uint4*)(g_ctx + (size_t)(m0 + orow) * Dd + k0 + owq * 8);
            float4 p0 = *(const float4*)(Wsel + (size_t)(n0 + onq) * Dd + k0 + okq * 8);
            float4 p1 = *(const float4*)(Wsel + (size_t)(n0 + onq) * Dd + k0 + okq * 8 + 4);
            rb = make_uint4(h2u(p0.x, p0.y), h2u(p0.z, p0.w),
                            h2u(p1.x, p1.y), h2u(p1.z, p1.w));
        }
        if (QKV) {
            *(uint2*)&As[0][am * SAW + ac * 2] = make_uint2(ra.x, ra.y);
            *(uint2*)&As[0][(am + 64) * SAW + ac * 2] = make_uint2(ra.z, ra.w);
            *(uint4*)&Bs[0][k2r * SBW + n4 * 4] = rb;
        } else {
            *(uint4*)&As[0][orow * SAW + owq * 4] = ra;
            Bs[0][(okq * 4 + 0) * SBW + onq] = rb.x;
            Bs[0][(okq * 4 + 1) * SBW + onq] = rb.y;
            Bs[0][(okq * 4 + 2) * SBW + onq] = rb.z;
            Bs[0][(okq * 4 + 3) * SBW + onq] = rb.w;
        }
    }
    __syncthreads();

    for (int kc = 0; kc < 64; ++kc) {
        const int buf = kc & 1;
        const bool more = (kc + 1 < 64);
        if (more) {
            const int k0 = (kc + 1) * 16;
            if (QKV) {
                float4 v0 = *(const float4*)(X + (size_t)(m0 + am) * Dd + k0 + ac * 4);
                float4 v1 = *(const float4*)(X + (size_t)(m0 + am + 64) * Dd + k0 + ac * 4);
                ra = make_uint4(h2u(v0.x, v0.y), h2u(v0.z, v0.w),
                                h2u(v1.x, v1.y), h2u(v1.z, v1.w));
                float4 w0 = *(const float4*)(Wsel + ((size_t)bh * Dd + k0 + 2 * k2r) * HD + be);
                float4 w1 = *(const float4*)(Wsel + ((size_t)bh * Dd + k0 + 2 * k2r + 1) * HD + be);
                rb = make_uint4(h2u(w0.x, w1.x), h2u(w0.y, w1.y),
                                h2u(w0.z, w1.z), h2u(w0.w, w1.w));
            } else {
                ra = *(const uint4*)(g_ctx + (size_t)(m0 + orow) * Dd + k0 + owq * 8);
                float4 p0 = *(const float4*)(Wsel + (size_t)(n0 + onq) * Dd + k0 + okq * 8);
                float4 p1 = *(const float4*)(Wsel + (size_t)(n0 + onq) * Dd + k0 + okq * 8 + 4);
                rb = make_uint4(h2u(p0.x, p0.y), h2u(p0.z, p0.w),
                                h2u(p1.x, p1.y), h2u(p1.z, p1.w));
            }
        }

        // ---- compute on buf ----
        {
            const uint32_t abase = asu + buf * ABUF;
            const uint32_t* bs = &Bs[buf][0];
            uint32_t af[4][4], bfr[4][2];
            #pragma unroll
            for (int ti = 0; ti < 4; ++ti)
                ldsm4(af[ti], abase +
                      ((uint32_t)(wm * 64 + ti * 16 + a_lrow) * SAW + a_lkw) * 4);
            #pragma unroll
            for (int tj = 0; tj < 4; ++tj) {
                const int cn = wn * 32 + tj * 8;
                bfr[tj][0] = bs[gx * SBW + cn + gy];
                bfr[tj][1] = bs[(gx + 4) * SBW + cn + gy];
            }
            #pragma unroll
            for (int ti = 0; ti < 4; ++ti)
                #pragma unroll
                for (int tj = 0; tj < 4; ++tj)
                    mma_f16(d[ti][tj], af[ti], bfr[tj]);
        }

        if (more) {
            const int nb = buf ^ 1;
            if (QKV) {
                *(uint2*)&As[nb][am * SAW + ac * 2] = make_uint2(ra.x, ra.y);
                *(uint2*)&As[nb][(am + 64) * SAW + ac * 2] = make_uint2(ra.z, ra.w);
                *(uint4*)&Bs[nb][k2r * SBW + n4 * 4] = rb;
            } else {
                *(uint4*)&As[nb][orow * SAW + owq * 4] = ra;
                Bs[nb][(okq * 4 + 0) * SBW + onq] = rb.x;
                Bs[nb][(okq * 4 + 1) * SBW + onq] = rb.y;
                Bs[nb][(okq * 4 + 2) * SBW + onq] = rb.z;
                Bs[nb][(okq * 4 + 3) * SBW + onq] = rb.w;
            }
        }
        __syncthreads();
    }

    // ---- epilogue ----
    if (QKV) {
        __half* out = (mtx == 0) ? g_q : (mtx == 1 ? g_k : g_v);
        const float sc = (mtx == 0) ? 0.125f : 1.0f;   // fold 1/sqrt(64) into Q
        #pragma unroll
        for (int ti = 0; ti < 4; ++ti) {
            #pragma unroll
            for (int tj = 0; tj < 4; ++tj) {
                const int colw = (nt & 7) * 128 + wn * 32 + tj * 8 + gx * 2;
                const int h = colw >> 6, e = colw & 63;
                const int r0 = m0 + wm * 64 + ti * 16 + gy;
                const int b0r = r0 >> 11, s0r = r0 & 2047;
                __half2 h2a = __floats2half2_rn(d[ti][tj][0] * sc, d[ti][tj][1] * sc);
                *(__half2*)(out + (((size_t)(b0r * Hh + h) * Ss + s0r) * HD + e)) = h2a;
                const int r1 = r0 + 8;
                const int b1r = r1 >> 11, s1r = r1 & 2047;
                __half2 h2b = __floats2half2_rn(d[ti][tj][2] * sc, d[ti][tj][3] * sc);
                *(__half2*)(out + (((size_t)(b1r * Hh + h) * Ss + s1r) * HD + e)) = h2b;
            }
        }
    } else {
        #pragma unroll
        for (int ti = 0; ti < 4; ++ti) {
            #pragma unroll
            for (int tj = 0; tj < 4; ++tj) {
                const int col = n0 + wn * 32 + tj * 8 + gx * 2;
                const float2 bv = *(const float2*)(bias + col);
                const int r0 = m0 + wm * 64 + ti * 16 + gy;
                *(float2*)(Cout + (size_t)r0 * Dd + col) =
                    make_float2(d[ti][tj][0] + bv.x, d[ti][tj][1] + bv.y);
                *(float2*)(Cout + (size_t)(r0 + 8) * Dd + col) =
                    make_float2(d[ti][tj][2] + bv.x, d[ti][tj][3] + bv.y);
            }
        }
    }
}

// ---------------------------------------------------------------------------
// fp16 mma causal flash attention. 8 warps x 16 q-rows per 128-q CTA.
// K/V 64x64 half tiles in smem (natural [j][e], stride 72 halfs = 144B rows).
// S fragments -> softmax (fp32) -> P packed straight into A-fragments (regs).
// ---------------------------------------------------------------------------
#define KST 36   // words per K/V smem row (32 data + 4 pad)

__global__ __launch_bounds__(256) void attn_f16_kernel()
{
    __shared__ uint32_t Ks[64 * KST];
    __shared__ uint32_t Vs[64 * KST];

    const int tid = threadIdx.x, wid = tid >> 5, lane = tid & 31;
    const int gy = lane >> 2, gx = lane & 3;
    const int b = blockIdx.z, h = blockIdx.y;
    const int qt = (int)gridDim.x - 1 - (int)blockIdx.x;   // big tiles first
    const int qbase = qt * 128 + wid * 16;
    const size_t bhofs = (size_t)(b * Hh + h) * Ss;

    const uint32_t ksu = smem_u32(Ks);
    const uint32_t vsu = smem_u32(Vs);
    const int lm = lane >> 3, lr = lane & 7;   // ldmatrix lane decode

    // Q fragments direct from gmem (g_q pre-scaled by 1/8)
    uint32_t qf[4][4];
    {
        const __half* Qg = g_q + (bhofs + qbase) * HD;
        #pragma unroll
        for (int ks = 0; ks < 4; ++ks) {
            qf[ks][0] = *(const uint32_t*)(Qg + gy * HD + ks * 16 + 2 * gx);
            qf[ks][1] = *(const uint32_t*)(Qg + (gy + 8) * HD + ks * 16 + 2 * gx);
            qf[ks][2] = *(const uint32_t*)(Qg + gy * HD + ks * 16 + 8 + 2 * gx);
            qf[ks][3] = *(const uint32_t*)(Qg + (gy + 8) * HD + ks * 16 + 8 + 2 * gx);
        }
    }

    float oa[8][4];
    #pragma unroll
    for (int tn = 0; tn < 8; ++tn)
        #pragma unroll
        for (int c = 0; c < 4; ++c) oa[tn][c] = 0.f;
    float m0 = -1e30f, m1 = -1e30f, l0 = 0.f, l1 = 0.f;

    const int lrow = tid >> 2, lwq = tid & 3;   // K/V loader mapping

    const int ntiles = qt * 2 + 2;
    for (int t64 = 0; t64 < ntiles; ++t64) {
        const int j0 = t64 * 64;
        __syncthreads();
        {
            const __half* Kg = g_k + (bhofs + j0) * HD;
            const __half* Vg = g_v + (bhofs + j0) * HD;
            const __half* kp = Kg + (size_t)lrow * HD + lwq * 16;
            const __half* vp = Vg + (size_t)lrow * HD + lwq * 16;
            *(uint4*)&Ks[lrow * KST + lwq * 8]     = *(const uint4*)(kp);
            *(uint4*)&Ks[lrow * KST + lwq * 8 + 4] = *(const uint4*)(kp + 8);
            *(uint4*)&Vs[lrow * KST + lwq * 8]     = *(const uint4*)(vp);
            *(uint4*)&Vs[lrow * KST + lwq * 8 + 4] = *(const uint4*)(vp + 8);
        }
        __syncthreads();
        if (j0 > qbase + 15) continue;   // fully masked for this warp

        // ---- S = Q @ K^T ----
        float s[8][4];
        #pragma unroll
        for (int tj = 0; tj < 8; ++tj)
            #pragma unroll
            for (int c = 0; c < 4; ++c) s[tj][c] = 0.f;
        #pragma unroll
        for (int ks = 0; ks < 4; ++ks) {
            #pragma unroll
            for (int p = 0; p < 4; ++p) {   // tj pairs
                uint32_t kb[4];
                ldsm4(kb, ksu + ((uint32_t)(p * 16 + (lm >> 1) * 8 + lr) * KST
                                 + ks * 8 + (lm & 1) * 4) * 4);
                mma_f16(s[2 * p],     qf[ks], &kb[0]);
                mma_f16(s[2 * p + 1], qf[ks], &kb[2]);
            }
        }

        const int r0 = qbase + gy, r1 = r0 + 8;
        if (j0 + 63 > qbase) {   // boundary tile: elementwise causal mask
            #pragma unroll
            for (int tj = 0; tj < 8; ++tj) {
                const int c = j0 + tj * 8 + gx * 2;
                if (c     > r0) s[tj][0] = -1e30f;
                if (c + 1 > r0) s[tj][1] = -1e30f;
                if (c     > r1) s[tj][2] = -1e30f;
                if (c + 1 > r1) s[tj][3] = -1e30f;
            }
        }

        // ---- online softmax (fp32) ----
        float mx0 = -1e30f, mx1 = -1e30f;
        #pragma unroll
        for (int tj = 0; tj < 8; ++tj) {
            mx0 = fmaxf(mx0, fmaxf(s[tj][0], s[tj][1]));
            mx1 = fmaxf(mx1, fmaxf(s[tj][2], s[tj][3]));
        }
        mx0 = fmaxf(mx0, __shfl_xor_sync(0xFFFFFFFFu, mx0, 1));
        mx0 = fmaxf(mx0, __shfl_xor_sync(0xFFFFFFFFu, mx0, 2));
        mx1 = fmaxf(mx1, __shfl_xor_sync(0xFFFFFFFFu, mx1, 1));
        mx1 = fmaxf(mx1, __shfl_xor_sync(0xFFFFFFFFu, mx1, 2));
        const float nm0 = fmaxf(m0, mx0), nm1 = fmaxf(m1, mx1);
        const float cr0 = __expf(m0 - nm0), cr1 = __expf(m1 - nm1);
        m0 = nm0; m1 = nm1;

        float sum0 = 0.f, sum1 = 0.f;
        #pragma unroll
        for (int tj = 0; tj < 8; ++tj) {
            s[tj][0] = __expf(s[tj][0] - m0);
            s[tj][1] = __expf(s[tj][1] - m0);
            s[tj][2] = __expf(s[tj][2] - m1);
            s[tj][3] = __expf(s[tj][3] - m1);
            sum0 += s[tj][0] + s[tj][1];
            sum1 += s[tj][2] + s[tj][3];
        }
        sum0 += __shfl_xor_sync(0xFFFFFFFFu, sum0, 1);
        sum0 += __shfl_xor_sync(0xFFFFFFFFu, sum0, 2);
        sum1 += __shfl_xor_sync(0xFFFFFFFFu, sum1, 1);
        sum1 += __shfl_xor_sync(0xFFFFFFFFu, sum1, 2);
        l0 = l0 * cr0 + sum0;
        l1 = l1 * cr1 + sum1;

        #pragma unroll
        for (int tn = 0; tn < 8; ++tn) {
            oa[tn][0] *= cr0; oa[tn][1] *= cr0;
            oa[tn][2] *= cr1; oa[tn][3] *= cr1;
        }

        // ---- pack P into A-fragments (registers only) ----
        uint32_t pk[4][4];
        #pragma unroll
        for (int ks = 0; ks < 4; ++ks) {
            pk[ks][0] = h2u(s[2 * ks][0], s[2 * ks][1]);
            pk[ks][1] = h2u(s[2 * ks][2], s[2 * ks][3]);
            pk[ks][2] = h2u(s[2 * ks + 1][0], s[2 * ks + 1][1]);
            pk[ks][3] = h2u(s[2 * ks + 1][2], s[2 * ks + 1][3]);
        }

        // ---- O += P @ V (V fragments via ldmatrix.trans) ----
        #pragma unroll
        for (int ks = 0; ks < 4; ++ks) {
            #pragma unroll
            for (int p = 0; p < 4; ++p) {   // tn pairs
                uint32_t vb[4];
                ldsm4t(vb, vsu + ((uint32_t)(ks * 16 + (lm & 1) * 8 + lr) * KST
                                  + p * 8 + (lm >> 1) * 4) * 4);
                mma_f16(oa[2 * p],     pk[ks], &vb[0]);
                mma_f16(oa[2 * p + 1], pk[ks], &vb[2]);
            }
        }
    }

    // ---- normalize & store to g_ctx (half) ----
    const float inv0 = 1.0f / l0, inv1 = 1.0f / l1;
    const int r0 = qbase + gy, r1 = r0 + 8;
    #pragma unroll
    for (int tn = 0; tn < 8; ++tn) {
        const int col = h * HD + tn * 8 + gx * 2;
        *(__half2*)(g_ctx + (size_t)(b * Ss + r0) * Dd + col) =
            __floats2half2_rn(oa[tn][0] * inv0, oa[tn][1] * inv0);
        *(__half2*)(g_ctx + (size_t)(b * Ss + r1) * Dd + col) =
            __floats2half2_rn(oa[tn][2] * inv1, oa[tn][3] * inv1);
    }
}

// ---------------------------------------------------------------------------
extern "C" void kernel_launch(void* const* d_in, const int* in_sizes, int n_in,
                              void* d_out, int out_size)
{
    const float* x  = (const float*)d_in[0];
    const float* Wq = (const float*)d_in[1];
    const float* Wk = (const float*)d_in[2];
    const float* Wv = (const float*)d_in[3];
    const float* Wo = (const float*)d_in[4];
    const float* bo = (const float*)d_in[5];
    float* y = (float*)d_out;

    dim3 gq(64, 24);     // M/128, 3 matrices x 8 n-tiles
    gemm_f16_kernel<1><<<gq, 256>>>(x, Wq, Wk, Wv, nullptr, nullptr, nullptr);

    dim3 ga(16, Hh, Bb); // q-tiles, heads, batch
    attn_f16_kernel<<<ga, 256>>>();

    dim3 go(64, 8);      // M/128, N/128
    gemm_f16_kernel<0><<<go, 256>>>(nullptr, nullptr, nullptr, nullptr, Wo, bo, y);
}

// round 6
// speedup vs baseline: 6.9986x; 1.4245x over previous
#include <cuda_runtime.h>
#include <cuda_fp16.h>
#include <math.h>
#include <stdint.h>

#define Bb 4
#define Ss 2048
#define Dd 1024
#define Hh 16
#define HD 64

// Device-global scratch (no allocations)
__device__ __half g_xh[8192*1024];      // x in fp16 [m][k]
__device__ __half g_wb[3072*1024];      // qkv weights fp16, [(mtx,h,e)][k]
__device__ __half g_woh[1024*1024];     // Wo fp16 [n][k]
__device__ __half g_q[Bb*Hh*Ss*HD];     // [B,H,S,HD], Q pre-scaled by 1/8
__device__ __half g_k[Bb*Hh*Ss*HD];
__device__ __half g_v[Bb*Hh*Ss*HD];
__device__ __half g_ctx[Bb*Ss*Dd];      // [B,S,D]

// ---------------------------------------------------------------------------
__device__ __forceinline__ uint32_t smem_u32(const void* p) {
    uint32_t a;
    asm("{ .reg .u64 t; cvta.to.shared.u64 t, %1; cvt.u32.u64 %0, t; }"
        : "=r"(a) : "l"(p));
    return a;
}
__device__ __forceinline__ uint32_t h2u(float a, float b) {
    __half2 h = __floats2half2_rn(a, b);
    return *(uint32_t*)&h;
}
__device__ __forceinline__ void mma_f16(float* d, const uint32_t* a,
                                        const uint32_t* b) {
    asm volatile(
        "mma.sync.aligned.m16n8k16.row.col.f32.f16.f16.f32 "
        "{%0,%1,%2,%3}, {%4,%5,%6,%7}, {%8,%9}, {%0,%1,%2,%3};"
        : "+f"(d[0]), "+f"(d[1]), "+f"(d[2]), "+f"(d[3])
        : "r"(a[0]), "r"(a[1]), "r"(a[2]), "r"(a[3]),
          "r"(b[0]), "r"(b[1]));
}
__device__ __forceinline__ void ldsm4(uint32_t* r, uint32_t a) {
    asm volatile("ldmatrix.sync.aligned.m8n8.x4.shared.b16 {%0,%1,%2,%3}, [%4];"
                 : "=r"(r[0]), "=r"(r[1]), "=r"(r[2]), "=r"(r[3]) : "r"(a));
}
__device__ __forceinline__ void ldsm4t(uint32_t* r, uint32_t a) {
    asm volatile("ldmatrix.sync.aligned.m8n8.x4.trans.shared.b16 {%0,%1,%2,%3}, [%4];"
                 : "=r"(r[0]), "=r"(r[1]), "=r"(r[2]), "=r"(r[3]) : "r"(a));
}
__device__ __forceinline__ void cpa16(uint32_t dst, const void* src) {
    asm volatile("cp.async.cg.shared.global [%0], [%1], 16;" :: "r"(dst), "l"(src));
}
#define CP_COMMIT() asm volatile("cp.async.commit_group;" ::: "memory")
template<int N> __device__ __forceinline__ void cpwait() {
    asm volatile("cp.async.wait_group %0;" :: "n"(N) : "memory");
}

// ---------------------------------------------------------------------------
// One-time conversions
// ---------------------------------------------------------------------------
__global__ __launch_bounds__(256) void convx_kernel(const float* __restrict__ x) {
    int i = blockIdx.x * 256 + threadIdx.x;          // n4 = 2097152
    float4 v = ((const float4*)x)[i];
    ((__half2*)g_xh)[2*i]   = __floats2half2_rn(v.x, v.y);
    ((__half2*)g_xh)[2*i+1] = __floats2half2_rn(v.z, v.w);
}
__global__ __launch_bounds__(256) void convwo_kernel(const float* __restrict__ Wo) {
    int i = blockIdx.x * 256 + threadIdx.x;          // n4 = 262144
    float4 v = ((const float4*)Wo)[i];
    ((__half2*)g_woh)[2*i]   = __floats2half2_rn(v.x, v.y);
    ((__half2*)g_woh)[2*i+1] = __floats2half2_rn(v.z, v.w);
}
// W[h][k][e] fp32 -> g_wb[(mtx*16+h)*64+e][k] fp16 (transpose)
__global__ __launch_bounds__(256) void convw_kernel(
    const float* __restrict__ Wq, const float* __restrict__ Wk,
    const float* __restrict__ Wv)
{
    __shared__ float tile[32][33];
    const int z = blockIdx.z, mtx = z >> 4, h = z & 15;
    const float* W = (mtx == 0) ? Wq : (mtx == 1 ? Wk : Wv);
    const int k0 = blockIdx.x * 32, e0 = blockIdx.y * 32;
    const int tx = threadIdx.x & 31, ty = threadIdx.x >> 5;
    #pragma unroll
    for (int r = 0; r < 4; ++r)
        tile[ty + r * 8][tx] = W[((size_t)h * Dd + k0 + ty + r * 8) * HD + e0 + tx];
    __syncthreads();
    #pragma unroll
    for (int r = 0; r < 4; ++r)
        g_wb[((size_t)(mtx * Hh + h) * HD + e0 + ty + r * 8) * Dd + k0 + tx] =
            __float2half(tile[tx][ty + r * 8]);
}

// ---------------------------------------------------------------------------
// cp.async fp16 GEMM: C[m][n] = sum_k A[m][k]*B[n][k], all operands fp16 gmem.
// CTA 128x128, BK=32, 4-stage pipeline, both fragments via ldmatrix.
// Row stride 80B (64B data + 16B pad): ldmatrix conflict-free.
// ---------------------------------------------------------------------------
#define STG_B 20480            // bytes per stage (A 10240 + B 10240)
#define GEMM_SMEM (4 * STG_B)  // 81920

template<int QKV>
__global__ __launch_bounds__(256, 2) void gemm_cp_kernel(
    const float* __restrict__ bias, float* __restrict__ Cout)
{
    extern __shared__ char dsm[];
    const uint32_t sbase = smem_u32(dsm);
    const int tid = threadIdx.x, wid = tid >> 5, lane = tid & 31;
    const int wm = wid >> 2, wn = wid & 3;
    const int gy = lane >> 2, gx = lane & 3;
    const int lm = lane >> 3, lr = lane & 7;
    const int a_lrow = (lm & 1) * 8 + lr, a_lhw = lane >> 4;
    const int m0 = blockIdx.x * 128, nt = blockIdx.y;
    const int bn0 = nt * 128;

    const __half* Ah = QKV ? g_xh : g_ctx;
    const __half* Bh = QKV ? g_wb : g_woh;

    const int lr2 = tid >> 2, cw = tid & 3;
    const __half* Abase = Ah + (size_t)(m0 + lr2) * Dd + cw * 8;
    const __half* Bbase = Bh + (size_t)(bn0 + lr2) * Dd + cw * 8;
    const uint32_t da0 = sbase + lr2 * 80 + cw * 16;
    const uint32_t da1 = sbase + (lr2 + 64) * 80 + cw * 16;
    const uint32_t db0 = da0 + 10240, db1 = da1 + 10240;

#define ISSUE(kc, slot) do {                                        \
    const uint32_t so = (uint32_t)(slot) * STG_B;                   \
    const __half* as_ = Abase + (kc) * 32;                          \
    const __half* bs_ = Bbase + (kc) * 32;                          \
    cpa16(da0 + so, as_);                                           \
    cpa16(da1 + so, as_ + 64 * Dd);                                 \
    cpa16(db0 + so, bs_);                                           \
    cpa16(db1 + so, bs_ + 64 * Dd);                                 \
    CP_COMMIT();                                                    \
} while (0)

    float d[4][4][4];
    #pragma unroll
    for (int i = 0; i < 4; i++)
        #pragma unroll
        for (int j = 0; j < 4; j++)
            #pragma unroll
            for (int c = 0; c < 4; c++) d[i][j][c] = 0.f;

    ISSUE(0, 0); ISSUE(1, 1); ISSUE(2, 2);

    for (int kc = 0; kc < 32; ++kc) {
        if (kc < 30) cpwait<2>();
        else if (kc == 30) cpwait<1>();
        else cpwait<0>();
        __syncthreads();
        if (kc + 3 < 32) ISSUE(kc + 3, (kc + 3) & 3);

        const uint32_t sa = sbase + (uint32_t)(kc & 3) * STG_B;
        const uint32_t sb = sa + 10240;
        #pragma unroll
        for (int ks = 0; ks < 2; ++ks) {
            uint32_t af[4][4];
            #pragma unroll
            for (int ti = 0; ti < 4; ++ti)
                ldsm4(af[ti], sa + (uint32_t)((wm * 64 + ti * 16 + a_lrow) * 80)
                              + ks * 32 + a_lhw * 16);
            #pragma unroll
            for (int nb = 0; nb < 2; ++nb) {
                uint32_t bf[4];
                ldsm4(bf, sb + (uint32_t)((wn * 32 + nb * 16 + (lm >> 1) * 8 + lr) * 80)
                          + ks * 32 + (lm & 1) * 16);
                #pragma unroll
                for (int ti = 0; ti < 4; ++ti) {
                    mma_f16(d[ti][nb * 2],     af[ti], &bf[0]);
                    mma_f16(d[ti][nb * 2 + 1], af[ti], &bf[2]);
                }
            }
        }
        __syncthreads();
    }
#undef ISSUE

    // ---- epilogue ----
    if (QKV) {
        const int mtx = nt >> 3;
        __half* out = (mtx == 0) ? g_q : (mtx == 1 ? g_k : g_v);
        const float sc = (mtx == 0) ? 0.125f : 1.0f;    // fold 1/sqrt(64) into Q
        #pragma unroll
        for (int ti = 0; ti < 4; ++ti) {
            #pragma unroll
            for (int tj = 0; tj < 4; ++tj) {
                const int colw = (nt & 7) * 128 + wn * 32 + tj * 8 + gx * 2;
                const int h = colw >> 6, e = colw & 63;
                const int r0 = m0 + wm * 64 + ti * 16 + gy;
                const int b0r = r0 >> 11, s0r = r0 & 2047;
                *(__half2*)(out + (((size_t)(b0r * Hh + h) * Ss + s0r) * HD + e)) =
                    __floats2half2_rn(d[ti][tj][0] * sc, d[ti][tj][1] * sc);
                const int r1 = r0 + 8;
                const int b1r = r1 >> 11, s1r = r1 & 2047;
                *(__half2*)(out + (((size_t)(b1r * Hh + h) * Ss + s1r) * HD + e)) =
                    __floats2half2_rn(d[ti][tj][2] * sc, d[ti][tj][3] * sc);
            }
        }
    } else {
        #pragma unroll
        for (int ti = 0; ti < 4; ++ti) {
            #pragma unroll
            for (int tj = 0; tj < 4; ++tj) {
                const int col = bn0 + wn * 32 + tj * 8 + gx * 2;
                const float2 bv = *(const float2*)(bias + col);
                const int r0 = m0 + wm * 64 + ti * 16 + gy;
                *(float2*)(Cout + (size_t)r0 * Dd + col) =
                    make_float2(d[ti][tj][0] + bv.x, d[ti][tj][1] + bv.y);
                *(float2*)(Cout + (size_t)(r0 + 8) * Dd + col) =
                    make_float2(d[ti][tj][2] + bv.x, d[ti][tj][3] + bv.y);
            }
        }
    }
}

// ---------------------------------------------------------------------------
// fp16 mma causal flash attention with cp.async triple-buffered K/V.
// 8 warps x 16 q-rows per 128-q CTA. K/V rows: 144B stride (128B data + pad).
// ---------------------------------------------------------------------------
#define KV_STG 9216                 // 64 * 144 bytes per operand-slot
#define ATTN_SMEM (6 * KV_STG)      // 3 K slots + 3 V slots = 55296

__global__ __launch_bounds__(256) void attn_cp_kernel()
{
    extern __shared__ char dsm[];
    const uint32_t sbase = smem_u32(dsm);
    const int tid = threadIdx.x, wid = tid >> 5, lane = tid & 31;
    const int gy = lane >> 2, gx = lane & 3;
    const int lm = lane >> 3, lr = lane & 7;
    const int b = blockIdx.z, h = blockIdx.y;
    const int qt = (int)gridDim.x - 1 - (int)blockIdx.x;
    const int qbase = qt * 128 + wid * 16;
    const size_t bhofs = (size_t)(b * Hh + h) * Ss;

    const int krow = tid >> 3, kc8 = tid & 7;
    const __half* Kb = g_k + (bhofs + krow) * HD + kc8 * 8;
    const __half* Vb = g_v + (bhofs + krow) * HD + kc8 * 8;
    const uint32_t dk = sbase + krow * 144 + kc8 * 16;
    const uint32_t dv = dk + 3 * KV_STG;

#define ISSUE_KV(t, slot) do {                                      \
    const uint32_t so = (uint32_t)(slot) * KV_STG;                  \
    const __half* kp = Kb + (size_t)(t) * 64 * HD;                  \
    const __half* vp = Vb + (size_t)(t) * 64 * HD;                  \
    cpa16(dk + so, kp);                                             \
    cpa16(dk + so + 32 * 144, kp + 32 * HD);                        \
    cpa16(dv + so, vp);                                             \
    cpa16(dv + so + 32 * 144, vp + 32 * HD);                        \
    CP_COMMIT();                                                    \
} while (0)

    // Q fragments direct from gmem (pre-scaled by 1/8)
    uint32_t qf[4][4];
    {
        const __half* Qg = g_q + (bhofs + qbase) * HD;
        #pragma unroll
        for (int ks = 0; ks < 4; ++ks) {
            qf[ks][0] = *(const uint32_t*)(Qg + gy * HD + ks * 16 + 2 * gx);
            qf[ks][1] = *(const uint32_t*)(Qg + (gy + 8) * HD + ks * 16 + 2 * gx);
            qf[ks][2] = *(const uint32_t*)(Qg + gy * HD + ks * 16 + 8 + 2 * gx);
            qf[ks][3] = *(const uint32_t*)(Qg + (gy + 8) * HD + ks * 16 + 8 + 2 * gx);
        }
    }

    float oa[8][4];
    #pragma unroll
    for (int tn = 0; tn < 8; ++tn)
        #pragma unroll
        for (int c = 0; c < 4; ++c) oa[tn][c] = 0.f;
    float m0 = -1e30f, m1 = -1e30f, l0 = 0.f, l1 = 0.f;

    const int ntiles = qt * 2 + 2;
    ISSUE_KV(0, 0);

    for (int t64 = 0; t64 < ntiles; ++t64) {
        if (t64 + 1 < ntiles) ISSUE_KV(t64 + 1, (t64 + 1) % 3);
        if (t64 + 2 <= ntiles) cpwait<1>(); else cpwait<0>();
        __syncthreads();

        const int j0 = t64 * 64;
        if (j0 <= qbase + 15) {
            const uint32_t ksu = sbase + (uint32_t)(t64 % 3) * KV_STG;
            const uint32_t vsu = ksu + 3 * KV_STG;

            // ---- S = Q @ K^T ----
            float s[8][4];
            #pragma unroll
            for (int tj = 0; tj < 8; ++tj)
                #pragma unroll
                for (int c = 0; c < 4; ++c) s[tj][c] = 0.f;
            #pragma unroll
            for (int ks = 0; ks < 4; ++ks) {
                #pragma unroll
                for (int p = 0; p < 4; ++p) {
                    uint32_t kb[4];
                    ldsm4(kb, ksu + (uint32_t)((p * 16 + (lm >> 1) * 8 + lr) * 144)
                              + ks * 32 + (lm & 1) * 16);
                    mma_f16(s[2 * p],     qf[ks], &kb[0]);
                    mma_f16(s[2 * p + 1], qf[ks], &kb[2]);
                }
            }

            const int r0 = qbase + gy, r1 = r0 + 8;
            if (j0 + 63 > qbase) {
                #pragma unroll
                for (int tj = 0; tj < 8; ++tj) {
                    const int c = j0 + tj * 8 + gx * 2;
                    if (c     > r0) s[tj][0] = -1e30f;
                    if (c + 1 > r0) s[tj][1] = -1e30f;
                    if (c     > r1) s[tj][2] = -1e30f;
                    if (c + 1 > r1) s[tj][3] = -1e30f;
                }
            }

            // ---- online softmax ----
            float mx0 = -1e30f, mx1 = -1e30f;
            #pragma unroll
            for (int tj = 0; tj < 8; ++tj) {
                mx0 = fmaxf(mx0, fmaxf(s[tj][0], s[tj][1]));
                mx1 = fmaxf(mx1, fmaxf(s[tj][2], s[tj][3]));
            }
            mx0 = fmaxf(mx0, __shfl_xor_sync(0xFFFFFFFFu, mx0, 1));
            mx0 = fmaxf(mx0, __shfl_xor_sync(0xFFFFFFFFu, mx0, 2));
            mx1 = fmaxf(mx1, __shfl_xor_sync(0xFFFFFFFFu, mx1, 1));
            mx1 = fmaxf(mx1, __shfl_xor_sync(0xFFFFFFFFu, mx1, 2));
            const float nm0 = fmaxf(m0, mx0), nm1 = fmaxf(m1, mx1);
            const float cr0 = __expf(m0 - nm0), cr1 = __expf(m1 - nm1);
            m0 = nm0; m1 = nm1;

            float sum0 = 0.f, sum1 = 0.f;
            #pragma unroll
            for (int tj = 0; tj < 8; ++tj) {
                s[tj][0] = __expf(s[tj][0] - m0);
                s[tj][1] = __expf(s[tj][1] - m0);
                s[tj][2] = __expf(s[tj][2] - m1);
                s[tj][3] = __expf(s[tj][3] - m1);
                sum0 += s[tj][0] + s[tj][1];
                sum1 += s[tj][2] + s[tj][3];
            }
            sum0 += __shfl_xor_sync(0xFFFFFFFFu, sum0, 1);
            sum0 += __shfl_xor_sync(0xFFFFFFFFu, sum0, 2);
            sum1 += __shfl_xor_sync(0xFFFFFFFFu, sum1, 1);
            sum1 += __shfl_xor_sync(0xFFFFFFFFu, sum1, 2);
            l0 = l0 * cr0 + sum0;
            l1 = l1 * cr1 + sum1;

            #pragma unroll
            for (int tn = 0; tn < 8; ++tn) {
                oa[tn][0] *= cr0; oa[tn][1] *= cr0;
                oa[tn][2] *= cr1; oa[tn][3] *= cr1;
            }

            // ---- pack P (registers) ----
            uint32_t pk[4][4];
            #pragma unroll
            for (int ks = 0; ks < 4; ++ks) {
                pk[ks][0] = h2u(s[2 * ks][0], s[2 * ks][1]);
                pk[ks][1] = h2u(s[2 * ks][2], s[2 * ks][3]);
                pk[ks][2] = h2u(s[2 * ks + 1][0], s[2 * ks + 1][1]);
                pk[ks][3] = h2u(s[2 * ks + 1][2], s[2 * ks + 1][3]);
            }

            // ---- O += P @ V ----
            #pragma unroll
            for (int ks = 0; ks < 4; ++ks) {
                #pragma unroll
                for (int p = 0; p < 4; ++p) {
                    uint32_t vb[4];
                    ldsm4t(vb, vsu + (uint32_t)((ks * 16 + (lm & 1) * 8 + lr) * 144)
                               + p * 32 + (lm >> 1) * 16);
                    mma_f16(oa[2 * p],     pk[ks], &vb[0]);
                    mma_f16(oa[2 * p + 1], pk[ks], &vb[2]);
                }
            }
        }
        __syncthreads();
    }
#undef ISSUE_KV

    // ---- normalize & store to g_ctx (half) ----
    const float inv0 = 1.0f / l0, inv1 = 1.0f / l1;
    const int r0 = qbase + gy, r1 = r0 + 8;
    #pragma unroll
    for (int tn = 0; tn < 8; ++tn) {
        const int col = h * HD + tn * 8 + gx * 2;
        *(__half2*)(g_ctx + (size_t)(b * Ss + r0) * Dd + col) =
            __floats2half2_rn(oa[tn][0] * inv0, oa[tn][1] * inv0);
        *(__half2*)(g_ctx + (size_t)(b * Ss + r1) * Dd + col) =
            __floats2half2_rn(oa[tn][2] * inv1, oa[tn][3] * inv1);
    }
}

// ---------------------------------------------------------------------------
extern "C" void kernel_launch(void* const* d_in, const int* in_sizes, int n_in,
                              void* d_out, int out_size)
{
    const float* x  = (const float*)d_in[0];
    const float* Wq = (const float*)d_in[1];
    const float* Wk = (const float*)d_in[2];
    const float* Wv = (const float*)d_in[3];
    const float* Wo = (const float*)d_in[4];
    const float* bo = (const float*)d_in[5];
    float* y = (float*)d_out;

    cudaFuncSetAttribute(gemm_cp_kernel<1>,
                         cudaFuncAttributeMaxDynamicSharedMemorySize, GEMM_SMEM);
    cudaFuncSetAttribute(gemm_cp_kernel<0>,
                         cudaFuncAttributeMaxDynamicSharedMemorySize, GEMM_SMEM);
    cudaFuncSetAttribute(attn_cp_kernel,
                         cudaFuncAttributeMaxDynamicSharedMemorySize, ATTN_SMEM);

    convx_kernel<<<8192, 256>>>(x);
    convwo_kernel<<<1024, 256>>>(Wo);
    dim3 gw(32, 2, 48);
    convw_kernel<<<gw, 256>>>(Wq, Wk, Wv);

    dim3 gq(64, 24);
    gemm_cp_kernel<1><<<gq, 256, GEMM_SMEM>>>(nullptr, nullptr);

    dim3 ga(16, Hh, Bb);
    attn_cp_kernel<<<ga, 256, ATTN_SMEM>>>();

    dim3 go(64, 8);
    gemm_cp_kernel<0><<<go, 256, GEMM_SMEM>>>(bo, y);
}

// round 7
// speedup vs baseline: 7.0292x; 1.0044x over previous
#include <cuda_runtime.h>
#include <cuda_fp16.h>
#include <math.h>
#include <stdint.h>

#define Bb 4
#define Ss 2048
#define Dd 1024
#define Hh 16
#define HD 64

// Device-global scratch (no allocations)
__device__ __half g_xh[8192*1024];      // x in fp16 [m][k]
__device__ __half g_wb[3072*1024];      // qkv weights fp16, [(mtx,h,e)][k]
__device__ __half g_woh[1024*1024];     // Wo fp16 [n][k]
__device__ __half g_q[Bb*Hh*Ss*HD];     // [B,H,S,HD], Q pre-scaled by 1/8
__device__ __half g_k[Bb*Hh*Ss*HD];
__device__ __half g_v[Bb*Hh*Ss*HD];
__device__ __half g_ctx[Bb*Ss*Dd];      // [B,S,D]

// ---------------------------------------------------------------------------
__device__ __forceinline__ uint32_t smem_u32(const void* p) {
    uint32_t a;
    asm("{ .reg .u64 t; cvta.to.shared.u64 t, %1; cvt.u32.u64 %0, t; }"
        : "=r"(a) : "l"(p));
    return a;
}
__device__ __forceinline__ uint32_t h2u(float a, float b) {
    __half2 h = __floats2half2_rn(a, b);
    return *(uint32_t*)&h;
}
__device__ __forceinline__ void mma_f16(float* d, const uint32_t* a,
                                        const uint32_t* b) {
    asm volatile(
        "mma.sync.aligned.m16n8k16.row.col.f32.f16.f16.f32 "
        "{%0,%1,%2,%3}, {%4,%5,%6,%7}, {%8,%9}, {%0,%1,%2,%3};"
        : "+f"(d[0]), "+f"(d[1]), "+f"(d[2]), "+f"(d[3])
        : "r"(a[0]), "r"(a[1]), "r"(a[2]), "r"(a[3]),
          "r"(b[0]), "r"(b[1]));
}
__device__ __forceinline__ void ldsm4(uint32_t* r, uint32_t a) {
    asm volatile("ldmatrix.sync.aligned.m8n8.x4.shared.b16 {%0,%1,%2,%3}, [%4];"
                 : "=r"(r[0]), "=r"(r[1]), "=r"(r[2]), "=r"(r[3]) : "r"(a));
}
__device__ __forceinline__ void ldsm4t(uint32_t* r, uint32_t a) {
    asm volatile("ldmatrix.sync.aligned.m8n8.x4.trans.shared.b16 {%0,%1,%2,%3}, [%4];"
                 : "=r"(r[0]), "=r"(r[1]), "=r"(r[2]), "=r"(r[3]) : "r"(a));
}
__device__ __forceinline__ void cpa16(uint32_t dst, const void* src) {
    asm volatile("cp.async.cg.shared.global [%0], [%1], 16;" :: "r"(dst), "l"(src));
}
#define CP_COMMIT() asm volatile("cp.async.commit_group;" ::: "memory")
template<int N> __device__ __forceinline__ void cpwait() {
    asm volatile("cp.async.wait_group %0;" :: "n"(N) : "memory");
}

// ---------------------------------------------------------------------------
// One-time conversions
// ---------------------------------------------------------------------------
__global__ __launch_bounds__(256) void convx_kernel(const float* __restrict__ x) {
    int i = blockIdx.x * 256 + threadIdx.x;
    float4 v = ((const float4*)x)[i];
    ((__half2*)g_xh)[2*i]   = __floats2half2_rn(v.x, v.y);
    ((__half2*)g_xh)[2*i+1] = __floats2half2_rn(v.z, v.w);
}
__global__ __launch_bounds__(256) void convwo_kernel(const float* __restrict__ Wo) {
    int i = blockIdx.x * 256 + threadIdx.x;
    float4 v = ((const float4*)Wo)[i];
    ((__half2*)g_woh)[2*i]   = __floats2half2_rn(v.x, v.y);
    ((__half2*)g_woh)[2*i+1] = __floats2half2_rn(v.z, v.w);
}
// W[h][k][e] fp32 -> g_wb[(mtx*16+h)*64+e][k] fp16 (transpose)
__global__ __launch_bounds__(256) void convw_kernel(
    const float* __restrict__ Wq, const float* __restrict__ Wk,
    const float* __restrict__ Wv)
{
    __shared__ float tile[32][33];
    const int z = blockIdx.z, mtx = z >> 4, h = z & 15;
    const float* W = (mtx == 0) ? Wq : (mtx == 1 ? Wk : Wv);
    const int k0 = blockIdx.x * 32, e0 = blockIdx.y * 32;
    const int tx = threadIdx.x & 31, ty = threadIdx.x >> 5;
    #pragma unroll
    for (int r = 0; r < 4; ++r)
        tile[ty + r * 8][tx] = W[((size_t)h * Dd + k0 + ty + r * 8) * HD + e0 + tx];
    __syncthreads();
    #pragma unroll
    for (int r = 0; r < 4; ++r)
        g_wb[((size_t)(mtx * Hh + h) * HD + e0 + ty + r * 8) * Dd + k0 + tx] =
            __float2half(tile[tx][ty + r * 8]);
}

// ---------------------------------------------------------------------------
// cp.async fp16 GEMM: C[m][n] = sum_k A[m][k]*B[n][k]. CTA 128x128, BK=32,
// 4-stage pipeline, ONE barrier per chunk, batched ldsm before mma.
// ---------------------------------------------------------------------------
#define STG_B 20480
#define GEMM_SMEM (4 * STG_B)

template<int QKV>
__global__ __launch_bounds__(256, 2) void gemm_cp_kernel(
    const float* __restrict__ bias, float* __restrict__ Cout)
{
    extern __shared__ char dsm[];
    const uint32_t sbase = smem_u32(dsm);
    const int tid = threadIdx.x, wid = tid >> 5, lane = tid & 31;
    const int wm = wid >> 2, wn = wid & 3;
    const int gy = lane >> 2, gx = lane & 3;
    const int lm = lane >> 3, lr = lane & 7;
    const int a_lrow = (lm & 1) * 8 + lr, a_lhw = lane >> 4;
    const int m0 = blockIdx.x * 128, nt = blockIdx.y;
    const int bn0 = nt * 128;

    const __half* Ah = QKV ? g_xh : g_ctx;
    const __half* Bh = QKV ? g_wb : g_woh;

    const int lr2 = tid >> 2, cw = tid & 3;
    const __half* Abase = Ah + (size_t)(m0 + lr2) * Dd + cw * 8;
    const __half* Bbase = Bh + (size_t)(bn0 + lr2) * Dd + cw * 8;
    const uint32_t da0 = sbase + lr2 * 80 + cw * 16;
    const uint32_t da1 = sbase + (lr2 + 64) * 80 + cw * 16;
    const uint32_t db0 = da0 + 10240, db1 = da1 + 10240;

    // precomputed fragment address offsets (within a stage)
    uint32_t aoff[4], boff[2];
    #pragma unroll
    for (int ti = 0; ti < 4; ++ti)
        aoff[ti] = (uint32_t)((wm * 64 + ti * 16 + a_lrow) * 80) + a_lhw * 16;
    #pragma unroll
    for (int nb = 0; nb < 2; ++nb)
        boff[nb] = 10240u + (uint32_t)((wn * 32 + nb * 16 + (lm >> 1) * 8 + lr) * 80)
                   + (lm & 1) * 16;

#define ISSUE(kc, slot) do {                                        \
    const uint32_t so = (uint32_t)(slot) * STG_B;                   \
    const __half* as_ = Abase + (kc) * 32;                          \
    const __half* bs_ = Bbase + (kc) * 32;                          \
    cpa16(da0 + so, as_);                                           \
    cpa16(da1 + so, as_ + 64 * Dd);                                 \
    cpa16(db0 + so, bs_);                                           \
    cpa16(db1 + so, bs_ + 64 * Dd);                                 \
    CP_COMMIT();                                                    \
} while (0)

    float d[4][4][4];
    #pragma unroll
    for (int i = 0; i < 4; i++)
        #pragma unroll
        for (int j = 0; j < 4; j++)
            #pragma unroll
            for (int c = 0; c < 4; c++) d[i][j][c] = 0.f;

    ISSUE(0, 0); ISSUE(1, 1); ISSUE(2, 2);

    for (int kc = 0; kc < 32; ++kc) {
        if (kc < 30) cpwait<2>();
        else if (kc == 30) cpwait<1>();
        else cpwait<0>();
        __syncthreads();                    // single barrier per chunk
        if (kc + 3 < 32) ISSUE(kc + 3, (kc + 3) & 3);

        const uint32_t sa = sbase + (uint32_t)(kc & 3) * STG_B;
        #pragma unroll
        for (int ks = 0; ks < 2; ++ks) {
            // batch all 6 ldsm, then all 16 mma
            uint32_t af[4][4], bf[2][4];
            #pragma unroll
            for (int ti = 0; ti < 4; ++ti)
                ldsm4(af[ti], sa + aoff[ti] + ks * 32);
            #pragma unroll
            for (int nb = 0; nb < 2; ++nb)
                ldsm4(bf[nb], sa + boff[nb] + ks * 32);
            #pragma unroll
            for (int nb = 0; nb < 2; ++nb)
                #pragma unroll
                for (int ti = 0; ti < 4; ++ti) {
                    mma_f16(d[ti][nb * 2],     af[ti], &bf[nb][0]);
                    mma_f16(d[ti][nb * 2 + 1], af[ti], &bf[nb][2]);
                }
        }
    }
#undef ISSUE

    // ---- epilogue ----
    if (QKV) {
        const int mtx = nt >> 3;
        __half* out = (mtx == 0) ? g_q : (mtx == 1 ? g_k : g_v);
        const float sc = (mtx == 0) ? 0.125f : 1.0f;
        #pragma unroll
        for (int ti = 0; ti < 4; ++ti) {
            #pragma unroll
            for (int tj = 0; tj < 4; ++tj) {
                const int colw = (nt & 7) * 128 + wn * 32 + tj * 8 + gx * 2;
                const int h = colw >> 6, e = colw & 63;
                const int r0 = m0 + wm * 64 + ti * 16 + gy;
                const int b0r = r0 >> 11, s0r = r0 & 2047;
                *(__half2*)(out + (((size_t)(b0r * Hh + h) * Ss + s0r) * HD + e)) =
                    __floats2half2_rn(d[ti][tj][0] * sc, d[ti][tj][1] * sc);
                const int r1 = r0 + 8;
                const int b1r = r1 >> 11, s1r = r1 & 2047;
                *(__half2*)(out + (((size_t)(b1r * Hh + h) * Ss + s1r) * HD + e)) =
                    __floats2half2_rn(d[ti][tj][2] * sc, d[ti][tj][3] * sc);
            }
        }
    } else {
        #pragma unroll
        for (int ti = 0; ti < 4; ++ti) {
            #pragma unroll
            for (int tj = 0; tj < 4; ++tj) {
                const int col = bn0 + wn * 32 + tj * 8 + gx * 2;
                const float2 bv = *(const float2*)(bias + col);
                const int r0 = m0 + wm * 64 + ti * 16 + gy;
                *(float2*)(Cout + (size_t)r0 * Dd + col) =
                    make_float2(d[ti][tj][0] + bv.x, d[ti][tj][1] + bv.y);
                *(float2*)(Cout + (size_t)(r0 + 8) * Dd + col) =
                    make_float2(d[ti][tj][2] + bv.x, d[ti][tj][3] + bv.y);
            }
        }
    }
}

// ---------------------------------------------------------------------------
// fp16 mma causal flash attention, cp.async triple-buffered K/V,
// ONE barrier per tile, batched ldsm before mma in both loops.
// ---------------------------------------------------------------------------
#define KV_STG 9216
#define ATTN_SMEM (6 * KV_STG)

__global__ __launch_bounds__(256) void attn_cp_kernel()
{
    extern __shared__ char dsm[];
    const uint32_t sbase = smem_u32(dsm);
    const int tid = threadIdx.x, wid = tid >> 5, lane = tid & 31;
    const int gy = lane >> 2, gx = lane & 3;
    const int lm = lane >> 3, lr = lane & 7;
    const int b = blockIdx.z, h = blockIdx.y;
    const int qt = (int)gridDim.x - 1 - (int)blockIdx.x;
    const int qbase = qt * 128 + wid * 16;
    const size_t bhofs = (size_t)(b * Hh + h) * Ss;

    const int krow = tid >> 3, kc8 = tid & 7;
    const __half* Kb = g_k + (bhofs + krow) * HD + kc8 * 8;
    const __half* Vb = g_v + (bhofs + krow) * HD + kc8 * 8;
    const uint32_t dk = sbase + krow * 144 + kc8 * 16;
    const uint32_t dv = dk + 3 * KV_STG;

    // precomputed fragment offsets within a K/V slot
    uint32_t koff[4], voff[4];
    #pragma unroll
    for (int p = 0; p < 4; ++p)
        koff[p] = (uint32_t)((p * 16 + (lm >> 1) * 8 + lr) * 144) + (lm & 1) * 16;
    #pragma unroll
    for (int ks = 0; ks < 4; ++ks)
        voff[ks] = (uint32_t)((ks * 16 + (lm & 1) * 8 + lr) * 144) + (lm >> 1) * 16;

#define ISSUE_KV(t, slot) do {                                      \
    const uint32_t so = (uint32_t)(slot) * KV_STG;                  \
    const __half* kp = Kb + (size_t)(t) * 64 * HD;                  \
    const __half* vp = Vb + (size_t)(t) * 64 * HD;                  \
    cpa16(dk + so, kp);                                             \
    cpa16(dk + so + 32 * 144, kp + 32 * HD);                        \
    cpa16(dv + so, vp);                                             \
    cpa16(dv + so + 32 * 144, vp + 32 * HD);                        \
    CP_COMMIT();                                                    \
} while (0)

    uint32_t qf[4][4];
    {
        const __half* Qg = g_q + (bhofs + qbase) * HD;
        #pragma unroll
        for (int ks = 0; ks < 4; ++ks) {
            qf[ks][0] = *(const uint32_t*)(Qg + gy * HD + ks * 16 + 2 * gx);
            qf[ks][1] = *(const uint32_t*)(Qg + (gy + 8) * HD + ks * 16 + 2 * gx);
            qf[ks][2] = *(const uint32_t*)(Qg + gy * HD + ks * 16 + 8 + 2 * gx);
            qf[ks][3] = *(const uint32_t*)(Qg + (gy + 8) * HD + ks * 16 + 8 + 2 * gx);
        }
    }

    float oa[8][4];
    #pragma unroll
    for (int tn = 0; tn < 8; ++tn)
        #pragma unroll
        for (int c = 0; c < 4; ++c) oa[tn][c] = 0.f;
    float m0 = -1e30f, m1 = -1e30f, l0 = 0.f, l1 = 0.f;

    const int ntiles = qt * 2 + 2;
    ISSUE_KV(0, 0);

    for (int t64 = 0; t64 < ntiles; ++t64) {
        if (t64 + 1 < ntiles) ISSUE_KV(t64 + 1, (t64 + 1) % 3);
        if (t64 + 2 <= ntiles) cpwait<1>(); else cpwait<0>();
        __syncthreads();                    // single barrier per tile

        const int j0 = t64 * 64;
        if (j0 <= qbase + 15) {
            const uint32_t ksu = sbase + (uint32_t)(t64 % 3) * KV_STG;
            const uint32_t vsu = ksu + 3 * KV_STG;

            // ---- S = Q @ K^T ----
            float s[8][4];
            #pragma unroll
            for (int tj = 0; tj < 8; ++tj)
                #pragma unroll
                for (int c = 0; c < 4; ++c) s[tj][c] = 0.f;
            #pragma unroll
            for (int ks = 0; ks < 4; ++ks) {
                uint32_t kb[4][4];
                #pragma unroll
                for (int p = 0; p < 4; ++p)
                    ldsm4(kb[p], ksu + koff[p] + ks * 32);
                #pragma unroll
                for (int p = 0; p < 4; ++p) {
                    mma_f16(s[2 * p],     qf[ks], &kb[p][0]);
                    mma_f16(s[2 * p + 1], qf[ks], &kb[p][2]);
                }
            }

            const int r0 = qbase + gy, r1 = r0 + 8;
            if (j0 + 63 > qbase) {
                #pragma unroll
                for (int tj = 0; tj < 8; ++tj) {
                    const int c = j0 + tj * 8 + gx * 2;
                    if (c     > r0) s[tj][0] = -1e30f;
                    if (c + 1 > r0) s[tj][1] = -1e30f;
                    if (c     > r1) s[tj][2] = -1e30f;
                    if (c + 1 > r1) s[tj][3] = -1e30f;
                }
            }

            // ---- online softmax ----
            float mx0 = -1e30f, mx1 = -1e30f;
            #pragma unroll
            for (int tj = 0; tj < 8; ++tj) {
                mx0 = fmaxf(mx0, fmaxf(s[tj][0], s[tj][1]));
                mx1 = fmaxf(mx1, fmaxf(s[tj][2], s[tj][3]));
            }
            mx0 = fmaxf(mx0, __shfl_xor_sync(0xFFFFFFFFu, mx0, 1));
            mx0 = fmaxf(mx0, __shfl_xor_sync(0xFFFFFFFFu, mx0, 2));
            mx1 = fmaxf(mx1, __shfl_xor_sync(0xFFFFFFFFu, mx1, 1));
            mx1 = fmaxf(mx1, __shfl_xor_sync(0xFFFFFFFFu, mx1, 2));
            const float nm0 = fmaxf(m0, mx0), nm1 = fmaxf(m1, mx1);
            const float cr0 = __expf(m0 - nm0), cr1 = __expf(m1 - nm1);
            m0 = nm0; m1 = nm1;

            float sum0 = 0.f, sum1 = 0.f;
            #pragma unroll
            for (int tj = 0; tj < 8; ++tj) {
                s[tj][0] = __expf(s[tj][0] - m0);
                s[tj][1] = __expf(s[tj][1] - m0);
                s[tj][2] = __expf(s[tj][2] - m1);
                s[tj][3] = __expf(s[tj][3] - m1);
                sum0 += s[tj][0] + s[tj][1];
                sum1 += s[tj][2] + s[tj][3];
            }
            sum0 += __shfl_xor_sync(0xFFFFFFFFu, sum0, 1);
            sum0 += __shfl_xor_sync(0xFFFFFFFFu, sum0, 2);
            sum1 += __shfl_xor_sync(0xFFFFFFFFu, sum1, 1);
            sum1 += __shfl_xor_sync(0xFFFFFFFFu, sum1, 2);
            l0 = l0 * cr0 + sum0;
            l1 = l1 * cr1 + sum1;

            #pragma unroll
            for (int tn = 0; tn < 8; ++tn) {
                oa[tn][0] *= cr0; oa[tn][1] *= cr0;
                oa[tn][2] *= cr1; oa[tn][3] *= cr1;
            }

            uint32_t pk[4][4];
            #pragma unroll
            for (int ks = 0; ks < 4; ++ks) {
                pk[ks][0] = h2u(s[2 * ks][0], s[2 * ks][1]);
                pk[ks][1] = h2u(s[2 * ks][2], s[2 * ks][3]);
                pk[ks][2] = h2u(s[2 * ks + 1][0], s[2 * ks + 1][1]);
                pk[ks][3] = h2u(s[2 * ks + 1][2], s[2 * ks + 1][3]);
            }

            // ---- O += P @ V ----
            #pragma unroll
            for (int ks = 0; ks < 4; ++ks) {
                uint32_t vb[4][4];
                #pragma unroll
                for (int p = 0; p < 4; ++p)
                    ldsm4t(vb[p], vsu + voff[ks] + p * 32);
                #pragma unroll
                for (int p = 0; p < 4; ++p) {
                    mma_f16(oa[2 * p],     pk[ks], &vb[p][0]);
                    mma_f16(oa[2 * p + 1], pk[ks], &vb[p][2]);
                }
            }
        }
    }
#undef ISSUE_KV

    const float inv0 = 1.0f / l0, inv1 = 1.0f / l1;
    const int r0 = qbase + gy, r1 = r0 + 8;
    #pragma unroll
    for (int tn = 0; tn < 8; ++tn) {
        const int col = h * HD + tn * 8 + gx * 2;
        *(__half2*)(g_ctx + (size_t)(b * Ss + r0) * Dd + col) =
            __floats2half2_rn(oa[tn][0] * inv0, oa[tn][1] * inv0);
        *(__half2*)(g_ctx + (size_t)(b * Ss + r1) * Dd + col) =
            __floats2half2_rn(oa[tn][2] * inv1, oa[tn][3] * inv1);
    }
}

// ---------------------------------------------------------------------------
extern "C" void kernel_launch(void* const* d_in, const int* in_sizes, int n_in,
                              void* d_out, int out_size)
{
    const float* x  = (const float*)d_in[0];
    const float* Wq = (const float*)d_in[1];
    const float* Wk = (const float*)d_in[2];
    const float* Wv = (const float*)d_in[3];
    const float* Wo = (const float*)d_in[4];
    const float* bo = (const float*)d_in[5];
    float* y = (float*)d_out;

    cudaFuncSetAttribute(gemm_cp_kernel<1>,
                         cudaFuncAttributeMaxDynamicSharedMemorySize, GEMM_SMEM);
    cudaFuncSetAttribute(gemm_cp_kernel<0>,
                         cudaFuncAttributeMaxDynamicSharedMemorySize, GEMM_SMEM);
    cudaFuncSetAttribute(attn_cp_kernel,
                         cudaFuncAttributeMaxDynamicSharedMemorySize, ATTN_SMEM);

    convx_kernel<<<8192, 256>>>(x);
    convwo_kernel<<<1024, 256>>>(Wo);
    dim3 gw(32, 2, 48);
    convw_kernel<<<gw, 256>>>(Wq, Wk, Wv);

    dim3 gq(64, 24);
    gemm_cp_kernel<1><<<gq, 256, GEMM_SMEM>>>(nullptr, nullptr);

    dim3 ga(16, Hh, Bb);
    attn_cp_kernel<<<ga, 256, ATTN_SMEM>>>();

    dim3 go(64, 8);
    gemm_cp_kernel<0><<<go, 256, GEMM_SMEM>>>(bo, y);
}

// round 8
// speedup vs baseline: 7.2270x; 1.0281x over previous
#include <cuda_runtime.h>
#include <cuda_fp16.h>
#include <math.h>
#include <stdint.h>

#define Bb 4
#define Ss 2048
#define Dd 1024
#define Hh 16
#define HD 64

// Device-global scratch (no allocations)
__device__ __half g_xh[8192*1024];      // x in fp16 [m][k]
__device__ __half g_wb[3072*1024];      // qkv weights fp16, [(mtx,h,e)][k]
__device__ __half g_woh[1024*1024];     // Wo fp16 [n][k]
__device__ __half g_q[Bb*Hh*Ss*HD];     // [B,H,S,HD], Q pre-scaled by 1/8
__device__ __half g_k[Bb*Hh*Ss*HD];
__device__ __half g_v[Bb*Hh*Ss*HD];
__device__ __half g_ctx[Bb*Ss*Dd];      // [B,S,D]

// ---------------------------------------------------------------------------
__device__ __forceinline__ uint32_t smem_u32(const void* p) {
    uint32_t a;
    asm("{ .reg .u64 t; cvta.to.shared.u64 t, %1; cvt.u32.u64 %0, t; }"
        : "=r"(a) : "l"(p));
    return a;
}
__device__ __forceinline__ uint32_t h2u(float a, float b) {
    __half2 h = __floats2half2_rn(a, b);
    return *(uint32_t*)&h;
}
__device__ __forceinline__ void mma_f16(float* d, const uint32_t* a,
                                        const uint32_t* b) {
    asm volatile(
        "mma.sync.aligned.m16n8k16.row.col.f32.f16.f16.f32 "
        "{%0,%1,%2,%3}, {%4,%5,%6,%7}, {%8,%9}, {%0,%1,%2,%3};"
        : "+f"(d[0]), "+f"(d[1]), "+f"(d[2]), "+f"(d[3])
        : "r"(a[0]), "r"(a[1]), "r"(a[2]), "r"(a[3]),
          "r"(b[0]), "r"(b[1]));
}
__device__ __forceinline__ void ldsm4(uint32_t* r, uint32_t a) {
    asm volatile("ldmatrix.sync.aligned.m8n8.x4.shared.b16 {%0,%1,%2,%3}, [%4];"
                 : "=r"(r[0]), "=r"(r[1]), "=r"(r[2]), "=r"(r[3]) : "r"(a));
}
__device__ __forceinline__ void ldsm4t(uint32_t* r, uint32_t a) {
    asm volatile("ldmatrix.sync.aligned.m8n8.x4.trans.shared.b16 {%0,%1,%2,%3}, [%4];"
                 : "=r"(r[0]), "=r"(r[1]), "=r"(r[2]), "=r"(r[3]) : "r"(a));
}
__device__ __forceinline__ void cpa16(uint32_t dst, const void* src) {
    asm volatile("cp.async.cg.shared.global [%0], [%1], 16;" :: "r"(dst), "l"(src));
}
#define CP_COMMIT() asm volatile("cp.async.commit_group;" ::: "memory")
template<int N> __device__ __forceinline__ void cpwait() {
    asm volatile("cp.async.wait_group %0;" :: "n"(N) : "memory");
}

// ---------------------------------------------------------------------------
// One-time conversions
// ---------------------------------------------------------------------------
__global__ __launch_bounds__(256) void convx_kernel(const float* __restrict__ x) {
    int i = blockIdx.x * 256 + threadIdx.x;
    float4 v = ((const float4*)x)[i];
    ((__half2*)g_xh)[2*i]   = __floats2half2_rn(v.x, v.y);
    ((__half2*)g_xh)[2*i+1] = __floats2half2_rn(v.z, v.w);
}
__global__ __launch_bounds__(256) void convwo_kernel(const float* __restrict__ Wo) {
    int i = blockIdx.x * 256 + threadIdx.x;
    float4 v = ((const float4*)Wo)[i];
    ((__half2*)g_woh)[2*i]   = __floats2half2_rn(v.x, v.y);
    ((__half2*)g_woh)[2*i+1] = __floats2half2_rn(v.z, v.w);
}
// W[h][k][e] fp32 -> g_wb[(mtx*16+h)*64+e][k] fp16 (transpose)
__global__ __launch_bounds__(256) void convw_kernel(
    const float* __restrict__ Wq, const float* __restrict__ Wk,
    const float* __restrict__ Wv)
{
    __shared__ float tile[32][33];
    const int z = blockIdx.z, mtx = z >> 4, h = z & 15;
    const float* W = (mtx == 0) ? Wq : (mtx == 1 ? Wk : Wv);
    const int k0 = blockIdx.x * 32, e0 = blockIdx.y * 32;
    const int tx = threadIdx.x & 31, ty = threadIdx.x >> 5;
    #pragma unroll
    for (int r = 0; r < 4; ++r)
        tile[ty + r * 8][tx] = W[((size_t)h * Dd + k0 + ty + r * 8) * HD + e0 + tx];
    __syncthreads();
    #pragma unroll
    for (int r = 0; r < 4; ++r)
        g_wb[((size_t)(mtx * Hh + h) * HD + e0 + ty + r * 8) * Dd + k0 + tx] =
            __float2half(tile[tx][ty + r * 8]);
}

// ---------------------------------------------------------------------------
// cp.async fp16 GEMM: CTA 128x128, BK=32, 4 stages, 4 warps (2x2), warp tile
// 64x64 -> 4 HMMA per ldsm (smem-port relief). 128 threads.
// ---------------------------------------------------------------------------
#define STG_B 20480
#define GEMM_SMEM (4 * STG_B)

template<int QKV>
__global__ __launch_bounds__(128, 2) void gemm_cp_kernel(
    const float* __restrict__ bias, float* __restrict__ Cout)
{
    extern __shared__ char dsm[];
    const uint32_t sbase = smem_u32(dsm);
    const int tid = threadIdx.x, wid = tid >> 5, lane = tid & 31;
    const int wm = wid >> 1, wn = wid & 1;          // 2 x 2 warp grid
    const int gy = lane >> 2, gx = lane & 3;
    const int lm = lane >> 3, lr = lane & 7;
    const int a_lrow = (lm & 1) * 8 + lr, a_lhw = lane >> 4;
    const int m0 = blockIdx.x * 128, nt = blockIdx.y;
    const int bn0 = nt * 128;

    const __half* Ah = QKV ? g_xh : g_ctx;
    const __half* Bh = QKV ? g_wb : g_woh;

    const int lr2 = tid >> 2, cw = tid & 3;         // 32 rows/pass, 4 passes
    const __half* Abase = Ah + (size_t)(m0 + lr2) * Dd + cw * 8;
    const __half* Bbase = Bh + (size_t)(bn0 + lr2) * Dd + cw * 8;
    const uint32_t da = sbase + lr2 * 80 + cw * 16;
    const uint32_t db = da + 10240;

    uint32_t aoff[4], boff[4];
    #pragma unroll
    for (int ti = 0; ti < 4; ++ti)
        aoff[ti] = (uint32_t)((wm * 64 + ti * 16 + a_lrow) * 80) + a_lhw * 16;
    #pragma unroll
    for (int nb = 0; nb < 4; ++nb)
        boff[nb] = 10240u + (uint32_t)((wn * 64 + nb * 16 + (lm >> 1) * 8 + lr) * 80)
                   + (lm & 1) * 16;

#define ISSUE(kc, slot) do {                                        \
    const uint32_t so = (uint32_t)(slot) * STG_B;                   \
    const __half* as_ = Abase + (kc) * 32;                          \
    const __half* bs_ = Bbase + (kc) * 32;                          \
    cpa16(da + so,             as_);                                \
    cpa16(da + so + 32 * 80,   as_ + 32 * Dd);                      \
    cpa16(da + so + 64 * 80,   as_ + 64 * Dd);                      \
    cpa16(da + so + 96 * 80,   as_ + 96 * Dd);                      \
    cpa16(db + so,             bs_);                                \
    cpa16(db + so + 32 * 80,   bs_ + 32 * Dd);                      \
    cpa16(db + so + 64 * 80,   bs_ + 64 * Dd);                      \
    cpa16(db + so + 96 * 80,   bs_ + 96 * Dd);                      \
    CP_COMMIT();                                                    \
} while (0)

    float d[4][8][4];
    #pragma unroll
    for (int i = 0; i < 4; i++)
        #pragma unroll
        for (int j = 0; j < 8; j++)
            #pragma unroll
            for (int c = 0; c < 4; c++) d[i][j][c] = 0.f;

    ISSUE(0, 0); ISSUE(1, 1); ISSUE(2, 2);

    for (int kc = 0; kc < 32; ++kc) {
        if (kc < 30) cpwait<2>();
        else if (kc == 30) cpwait<1>();
        else cpwait<0>();
        __syncthreads();
        if (kc + 3 < 32) ISSUE(kc + 3, (kc + 3) & 3);

        const uint32_t sa = sbase + (uint32_t)(kc & 3) * STG_B;
        #pragma unroll
        for (int ks = 0; ks < 2; ++ks) {
            uint32_t af[4][4], bf[4][4];
            #pragma unroll
            for (int ti = 0; ti < 4; ++ti)
                ldsm4(af[ti], sa + aoff[ti] + ks * 32);
            #pragma unroll
            for (int nb = 0; nb < 4; ++nb)
                ldsm4(bf[nb], sa + boff[nb] + ks * 32);
            #pragma unroll
            for (int nb = 0; nb < 4; ++nb)
                #pragma unroll
                for (int ti = 0; ti < 4; ++ti) {
                    mma_f16(d[ti][nb * 2],     af[ti], &bf[nb][0]);
                    mma_f16(d[ti][nb * 2 + 1], af[ti], &bf[nb][2]);
                }
        }
    }
#undef ISSUE

    // ---- epilogue (warp covers 64x64) ----
    if (QKV) {
        const int mtx = nt >> 3;
        __half* out = (mtx == 0) ? g_q : (mtx == 1 ? g_k : g_v);
        const float sc = (mtx == 0) ? 0.125f : 1.0f;
        #pragma unroll
        for (int ti = 0; ti < 4; ++ti) {
            #pragma unroll
            for (int tj = 0; tj < 8; ++tj) {
                const int colw = (nt & 7) * 128 + wn * 64 + tj * 8 + gx * 2;
                const int h = colw >> 6, e = colw & 63;
                const int r0 = m0 + wm * 64 + ti * 16 + gy;
                const int b0r = r0 >> 11, s0r = r0 & 2047;
                *(__half2*)(out + (((size_t)(b0r * Hh + h) * Ss + s0r) * HD + e)) =
                    __floats2half2_rn(d[ti][tj][0] * sc, d[ti][tj][1] * sc);
                const int r1 = r0 + 8;
                const int b1r = r1 >> 11, s1r = r1 & 2047;
                *(__half2*)(out + (((size_t)(b1r * Hh + h) * Ss + s1r) * HD + e)) =
                    __floats2half2_rn(d[ti][tj][2] * sc, d[ti][tj][3] * sc);
            }
        }
    } else {
        #pragma unroll
        for (int ti = 0; ti < 4; ++ti) {
            #pragma unroll
            for (int tj = 0; tj < 8; ++tj) {
                const int col = bn0 + wn * 64 + tj * 8 + gx * 2;
                const float2 bv = *(const float2*)(bias + col);
                const int r0 = m0 + wm * 64 + ti * 16 + gy;
                *(float2*)(Cout + (size_t)r0 * Dd + col) =
                    make_float2(d[ti][tj][0] + bv.x, d[ti][tj][1] + bv.y);
                *(float2*)(Cout + (size_t)(r0 + 8) * Dd + col) =
                    make_float2(d[ti][tj][2] + bv.x, d[ti][tj][3] + bv.y);
            }
        }
    }
}

// ---------------------------------------------------------------------------
// fp16 mma causal flash attention. 4 warps x 32 q-rows per 128-q CTA,
// cp.async triple-buffered K/V, 4 HMMA per ldsm.
// ---------------------------------------------------------------------------
#define KV_STG 9216
#define ATTN_SMEM (6 * KV_STG)

__global__ __launch_bounds__(128, 2) void attn_cp_kernel()
{
    extern __shared__ char dsm[];
    const uint32_t sbase = smem_u32(dsm);
    const int tid = threadIdx.x, wid = tid >> 5, lane = tid & 31;
    const int gy = lane >> 2, gx = lane & 3;
    const int lm = lane >> 3, lr = lane & 7;
    const int b = blockIdx.z, h = blockIdx.y;
    const int qt = (int)gridDim.x - 1 - (int)blockIdx.x;
    const int qbase = qt * 128 + wid * 32;          // 32 rows per warp
    const size_t bhofs = (size_t)(b * Hh + h) * Ss;

    const int krow = tid >> 1;                       // 2 threads per 64-row
    const int kcb = (tid & 1) * 32;                  // half-row (halfs)
    const __half* Kb = g_k + (bhofs + krow) * HD + kcb;
    const __half* Vb = g_v + (bhofs + krow) * HD + kcb;
    const uint32_t dk = sbase + krow * 144 + kcb * 2;
    const uint32_t dv = dk + 3 * KV_STG;

    uint32_t koff[4], voff[4];
    #pragma unroll
    for (int p = 0; p < 4; ++p)
        koff[p] = (uint32_t)((p * 16 + (lm >> 1) * 8 + lr) * 144) + (lm & 1) * 16;
    #pragma unroll
    for (int ks = 0; ks < 4; ++ks)
        voff[ks] = (uint32_t)((ks * 16 + (lm & 1) * 8 + lr) * 144) + (lm >> 1) * 16;

#define ISSUE_KV(t, slot) do {                                      \
    const uint32_t so = (uint32_t)(slot) * KV_STG;                  \
    const __half* kp = Kb + (size_t)(t) * 64 * HD;                  \
    const __half* vp = Vb + (size_t)(t) * 64 * HD;                  \
    cpa16(dk + so,      kp);                                        \
    cpa16(dk + so + 16, kp + 8);                                    \
    cpa16(dk + so + 32, kp + 16);                                   \
    cpa16(dk + so + 48, kp + 24);                                   \
    cpa16(dv + so,      vp);                                        \
    cpa16(dv + so + 16, vp + 8);                                    \
    cpa16(dv + so + 32, vp + 16);                                   \
    cpa16(dv + so + 48, vp + 24);                                   \
    CP_COMMIT();                                                    \
} while (0)

    // Q fragments, two 16-row sub-tiles per warp (pre-scaled by 1/8)
    uint32_t qf[2][4][4];
    #pragma unroll
    for (int mt = 0; mt < 2; ++mt) {
        const __half* Qg = g_q + (bhofs + qbase + mt * 16) * HD;
        #pragma unroll
        for (int ks = 0; ks < 4; ++ks) {
            qf[mt][ks][0] = *(const uint32_t*)(Qg + gy * HD + ks * 16 + 2 * gx);
            qf[mt][ks][1] = *(const uint32_t*)(Qg + (gy + 8) * HD + ks * 16 + 2 * gx);
            qf[mt][ks][2] = *(const uint32_t*)(Qg + gy * HD + ks * 16 + 8 + 2 * gx);
            qf[mt][ks][3] = *(const uint32_t*)(Qg + (gy + 8) * HD + ks * 16 + 8 + 2 * gx);
        }
    }

    float oa[2][8][4];
    #pragma unroll
    for (int mt = 0; mt < 2; ++mt)
        #pragma unroll
        for (int tn = 0; tn < 8; ++tn)
            #pragma unroll
            for (int c = 0; c < 4; ++c) oa[mt][tn][c] = 0.f;
    float mrow[2][2] = {{-1e30f, -1e30f}, {-1e30f, -1e30f}};
    float lrow[2][2] = {{0.f, 0.f}, {0.f, 0.f}};

    const int ntiles = qt * 2 + 2;
    ISSUE_KV(0, 0);

    for (int t64 = 0; t64 < ntiles; ++t64) {
        if (t64 + 1 < ntiles) ISSUE_KV(t64 + 1, (t64 + 1) % 3);
        if (t64 + 2 <= ntiles) cpwait<1>(); else cpwait<0>();
        __syncthreads();

        const int j0 = t64 * 64;
        if (j0 <= qbase + 31) {
            const uint32_t ksu = sbase + (uint32_t)(t64 % 3) * KV_STG;
            const uint32_t vsu = ksu + 3 * KV_STG;

            // ---- S = Q @ K^T (two 16-row sub-tiles share K fragments) ----
            float s[2][8][4];
            #pragma unroll
            for (int mt = 0; mt < 2; ++mt)
                #pragma unroll
                for (int tj = 0; tj < 8; ++tj)
                    #pragma unroll
                    for (int c = 0; c < 4; ++c) s[mt][tj][c] = 0.f;
            #pragma unroll
            for (int ks = 0; ks < 4; ++ks) {
                uint32_t kb[4][4];
                #pragma unroll
                for (int p = 0; p < 4; ++p)
                    ldsm4(kb[p], ksu + koff[p] + ks * 32);
                #pragma unroll
                for (int p = 0; p < 4; ++p)
                    #pragma unroll
                    for (int mt = 0; mt < 2; ++mt) {
                        mma_f16(s[mt][2 * p],     qf[mt][ks], &kb[p][0]);
                        mma_f16(s[mt][2 * p + 1], qf[mt][ks], &kb[p][2]);
                    }
            }

            // ---- causal mask (boundary tiles only) ----
            if (j0 + 63 > qbase) {
                #pragma unroll
                for (int mt = 0; mt < 2; ++mt) {
                    const int r0 = qbase + mt * 16 + gy, r1 = r0 + 8;
                    #pragma unroll
                    for (int tj = 0; tj < 8; ++tj) {
                        const int c = j0 + tj * 8 + gx * 2;
                        if (c     > r0) s[mt][tj][0] = -1e30f;
                        if (c + 1 > r0) s[mt][tj][1] = -1e30f;
                        if (c     > r1) s[mt][tj][2] = -1e30f;
                        if (c + 1 > r1) s[mt][tj][3] = -1e30f;
                    }
                }
            }

            // ---- online softmax + pack P ----
            uint32_t pk[2][4][4];
            #pragma unroll
            for (int mt = 0; mt < 2; ++mt) {
                float mx0 = -1e30f, mx1 = -1e30f;
                #pragma unroll
                for (int tj = 0; tj < 8; ++tj) {
                    mx0 = fmaxf(mx0, fmaxf(s[mt][tj][0], s[mt][tj][1]));
                    mx1 = fmaxf(mx1, fmaxf(s[mt][tj][2], s[mt][tj][3]));
                }
                mx0 = fmaxf(mx0, __shfl_xor_sync(0xFFFFFFFFu, mx0, 1));
                mx0 = fmaxf(mx0, __shfl_xor_sync(0xFFFFFFFFu, mx0, 2));
                mx1 = fmaxf(mx1, __shfl_xor_sync(0xFFFFFFFFu, mx1, 1));
                mx1 = fmaxf(mx1, __shfl_xor_sync(0xFFFFFFFFu, mx1, 2));
                const float nm0 = fmaxf(mrow[mt][0], mx0);
                const float nm1 = fmaxf(mrow[mt][1], mx1);
                const float cr0 = __expf(mrow[mt][0] - nm0);
                const float cr1 = __expf(mrow[mt][1] - nm1);
                mrow[mt][0] = nm0; mrow[mt][1] = nm1;

                float sum0 = 0.f, sum1 = 0.f;
                #pragma unroll
                for (int tj = 0; tj < 8; ++tj) {
                    s[mt][tj][0] = __expf(s[mt][tj][0] - nm0);
                    s[mt][tj][1] = __expf(s[mt][tj][1] - nm0);
                    s[mt][tj][2] = __expf(s[mt][tj][2] - nm1);
                    s[mt][tj][3] = __expf(s[mt][tj][3] - nm1);
                    sum0 += s[mt][tj][0] + s[mt][tj][1];
                    sum1 += s[mt][tj][2] + s[mt][tj][3];
                }
                sum0 += __shfl_xor_sync(0xFFFFFFFFu, sum0, 1);
                sum0 += __shfl_xor_sync(0xFFFFFFFFu, sum0, 2);
                sum1 += __shfl_xor_sync(0xFFFFFFFFu, sum1, 1);
                sum1 += __shfl_xor_sync(0xFFFFFFFFu, sum1, 2);
                lrow[mt][0] = lrow[mt][0] * cr0 + sum0;
                lrow[mt][1] = lrow[mt][1] * cr1 + sum1;

                #pragma unroll
                for (int tn = 0; tn < 8; ++tn) {
                    oa[mt][tn][0] *= cr0; oa[mt][tn][1] *= cr0;
                    oa[mt][tn][2] *= cr1; oa[mt][tn][3] *= cr1;
                }
                #pragma unroll
                for (int ks = 0; ks < 4; ++ks) {
                    pk[mt][ks][0] = h2u(s[mt][2 * ks][0], s[mt][2 * ks][1]);
                    pk[mt][ks][1] = h2u(s[mt][2 * ks][2], s[mt][2 * ks][3]);
                    pk[mt][ks][2] = h2u(s[mt][2 * ks + 1][0], s[mt][2 * ks + 1][1]);
                    pk[mt][ks][3] = h2u(s[mt][2 * ks + 1][2], s[mt][2 * ks + 1][3]);
                }
            }

            // ---- O += P @ V (sub-tiles share V fragments) ----
            #pragma unroll
            for (int ks = 0; ks < 4; ++ks) {
                uint32_t vb[4][4];
                #pragma unroll
                for (int p = 0; p < 4; ++p)
                    ldsm4t(vb[p], vsu + voff[ks] + p * 32);
                #pragma unroll
                for (int p = 0; p < 4; ++p)
                    #pragma unroll
                    for (int mt = 0; mt < 2; ++mt) {
                        mma_f16(oa[mt][2 * p],     pk[mt][ks], &vb[p][0]);
                        mma_f16(oa[mt][2 * p + 1], pk[mt][ks], &vb[p][2]);
                    }
            }
        }
    }
#undef ISSUE_KV

    // ---- normalize & store to g_ctx (half) ----
    #pragma unroll
    for (int mt = 0; mt < 2; ++mt) {
        const float inv0 = 1.0f / lrow[mt][0], inv1 = 1.0f / lrow[mt][1];
        const int r0 = qbase + mt * 16 + gy, r1 = r0 + 8;
        #pragma unroll
        for (int tn = 0; tn < 8; ++tn) {
            const int col = h * HD + tn * 8 + gx * 2;
            *(__half2*)(g_ctx + (size_t)(b * Ss + r0) * Dd + col) =
                __floats2half2_rn(oa[mt][tn][0] * inv0, oa[mt][tn][1] * inv0);
            *(__half2*)(g_ctx + (size_t)(b * Ss + r1) * Dd + col) =
                __floats2half2_rn(oa[mt][tn][2] * inv1, oa[mt][tn][3] * inv1);
        }
    }
}

// ---------------------------------------------------------------------------
extern "C" void kernel_launch(void* const* d_in, const int* in_sizes, int n_in,
                              void* d_out, int out_size)
{
    const float* x  = (const float*)d_in[0];
    const float* Wq = (const float*)d_in[1];
    const float* Wk = (const float*)d_in[2];
    const float* Wv = (const float*)d_in[3];
    const float* Wo = (const float*)d_in[4];
    const float* bo = (const float*)d_in[5];
    float* y = (float*)d_out;

    cudaFuncSetAttribute(gemm_cp_kernel<1>,
                         cudaFuncAttributeMaxDynamicSharedMemorySize, GEMM_SMEM);
    cudaFuncSetAttribute(gemm_cp_kernel<0>,
                         cudaFuncAttributeMaxDynamicSharedMemorySize, GEMM_SMEM);
    cudaFuncSetAttribute(attn_cp_kernel,
                         cudaFuncAttributeMaxDynamicSharedMemorySize, ATTN_SMEM);

    convx_kernel<<<8192, 256>>>(x);
    convwo_kernel<<<1024, 256>>>(Wo);
    dim3 gw(32, 2, 48);
    convw_kernel<<<gw, 256>>>(Wq, Wk, Wv);

    dim3 gq(64, 24);
    gemm_cp_kernel<1><<<gq, 128, GEMM_SMEM>>>(nullptr, nullptr);

    dim3 ga(16, Hh, Bb);
    attn_cp_kernel<<<ga, 128, ATTN_SMEM>>>();

    dim3 go(64, 8);
    gemm_cp_kernel<0><<<go, 128, GEMM_SMEM>>>(bo, y);
}